// round 1
// baseline (speedup 1.0000x reference)
#include <cuda_runtime.h>
#include <cuda_bf16.h>
#include <math.h>

// Problem constants
#define BATCH 16
#define C 384
#define HH 56
#define WW 56
#define HW (HH*WW)            // 3136
#define NTOK (BATCH*HW)       // 50176
#define HEADS 12
#define DHEAD 32
#define WS 14
#define NWIN_SIDE 4           // 56/14
#define WIN_PER_B 16
#define NWIN (BATCH*WIN_PER_B) // 256
#define NTOKW (WS*WS)          // 196
#define MLP_HID (4*C)          // 1536
#define QKV_DIM (3*C)          // 1152

// ---------------- scratch buffers (device globals; no runtime allocation) ----
__device__ float g_x1[(size_t)NTOK * C];       // conv+residual output (BHWC), attention shortcut
__device__ float g_xn[(size_t)NTOK * C];       // LN output (reused for LN1 and LN2)
__device__ float g_qkv[(size_t)NTOK * QKV_DIM];
__device__ float g_attn[(size_t)NTOK * C];
__device__ float g_x2[(size_t)NTOK * C];       // after proj + residual
__device__ float g_h[(size_t)NTOK * MLP_HID];  // MLP hidden
__device__ float g_x3[(size_t)NTOK * C];       // final BHWC before transpose

// ---------------- kernel 1: depthwise 3x3 conv + bias + residual, NCHW -> BHWC
__global__ void conv_pe_kernel(const float* __restrict__ x,
                               const float* __restrict__ cw,
                               const float* __restrict__ cb,
                               float* __restrict__ out)
{
    int pix = blockIdx.x;            // b*HW + h*W + w
    int c = threadIdx.x;             // 0..383
    int b = pix / HW;
    int hw = pix - b * HW;
    int h = hw / WW;
    int w = hw - h * WW;

    const float* xc = x + ((size_t)(b * C + c)) * HW;
    const float* wc = cw + c * 9;

    float s = cb[c] + xc[h * WW + w];   // bias + residual
    #pragma unroll
    for (int dy = -1; dy <= 1; dy++) {
        int hh = h + dy;
        if (hh < 0 || hh >= HH) continue;
        #pragma unroll
        for (int dx = -1; dx <= 1; dx++) {
            int ww = w + dx;
            if (ww < 0 || ww >= WW) continue;
            s += xc[hh * WW + ww] * wc[(dy + 1) * 3 + (dx + 1)];
        }
    }
    out[(size_t)pix * C + c] = s;
}

// ---------------- layer norm over C=384 (one block per token, 128 threads) ---
__global__ void ln_kernel(const float* __restrict__ x,
                          const float* __restrict__ w,
                          const float* __restrict__ b,
                          float* __restrict__ y)
{
    __shared__ float red[4];
    int t = blockIdx.x;
    int tid = threadIdx.x;
    const float* xr = x + (size_t)t * C;

    float v0 = xr[tid];
    float v1 = xr[tid + 128];
    float v2 = xr[tid + 256];

    // sum
    float s = v0 + v1 + v2;
    for (int o = 16; o > 0; o >>= 1) s += __shfl_down_sync(0xffffffffu, s, o);
    if ((tid & 31) == 0) red[tid >> 5] = s;
    __syncthreads();
    float tot = red[0] + red[1] + red[2] + red[3];
    float mean = tot * (1.0f / C);

    // variance
    float d0 = v0 - mean, d1 = v1 - mean, d2 = v2 - mean;
    float q = d0 * d0 + d1 * d1 + d2 * d2;
    __syncthreads();
    for (int o = 16; o > 0; o >>= 1) q += __shfl_down_sync(0xffffffffu, q, o);
    if ((tid & 31) == 0) red[tid >> 5] = q;
    __syncthreads();
    float var = (red[0] + red[1] + red[2] + red[3]) * (1.0f / C);
    float rstd = rsqrtf(var + 1e-5f);

    float* yr = y + (size_t)t * C;
    yr[tid]       = d0 * rstd * w[tid]       + b[tid];
    yr[tid + 128] = d1 * rstd * w[tid + 128] + b[tid + 128];
    yr[tid + 256] = d2 * rstd * w[tid + 256] + b[tid + 256];
}

// ---------------- SGEMM: out[M,N] = A[M,K] @ W[N,K]^T (+bias)(+res)(+gelu) ---
// EPI: 0 = plain, 1 = +bias +residual, 2 = +bias then exact GELU
// BM=BN=128, BK=8, 256 threads, 8x8 per thread (split 4+4 layout).
template<int EPI>
__global__ void __launch_bounds__(256, 2)
sgemm_kernel(const float* __restrict__ A, const float* __restrict__ W,
             const float* __restrict__ bias, const float* __restrict__ res,
             float* __restrict__ out, int M, int N, int K)
{
    __shared__ float As[8][128];
    __shared__ float Bs[8][128];

    int tid = threadIdx.x;
    int tx = tid & 15;          // 0..15
    int ty = tid >> 4;          // 0..15
    int bx = blockIdx.x;        // N tile
    int by = blockIdx.y;        // M tile

    int arow = tid >> 1;
    int acol = (tid & 1) * 4;
    const float* Aload = A + (size_t)(by * 128 + arow) * K + acol;
    const float* Wload = W + (size_t)(bx * 128 + arow) * K + acol;

    float acc[8][8];
    #pragma unroll
    for (int i = 0; i < 8; i++)
        #pragma unroll
        for (int j = 0; j < 8; j++) acc[i][j] = 0.f;

    for (int kt = 0; kt < K; kt += 8) {
        float4 av = *(const float4*)(Aload + kt);
        float4 bv = *(const float4*)(Wload + kt);
        As[acol + 0][arow] = av.x;
        As[acol + 1][arow] = av.y;
        As[acol + 2][arow] = av.z;
        As[acol + 3][arow] = av.w;
        Bs[acol + 0][arow] = bv.x;
        Bs[acol + 1][arow] = bv.y;
        Bs[acol + 2][arow] = bv.z;
        Bs[acol + 3][arow] = bv.w;
        __syncthreads();

        #pragma unroll
        for (int k = 0; k < 8; k++) {
            float a[8], bb[8];
            *(float4*)&a[0]  = *(const float4*)&As[k][ty * 4];
            *(float4*)&a[4]  = *(const float4*)&As[k][64 + ty * 4];
            *(float4*)&bb[0] = *(const float4*)&Bs[k][tx * 4];
            *(float4*)&bb[4] = *(const float4*)&Bs[k][64 + tx * 4];
            #pragma unroll
            for (int i = 0; i < 8; i++)
                #pragma unroll
                for (int j = 0; j < 8; j++)
                    acc[i][j] = fmaf(a[i], bb[j], acc[i][j]);
        }
        __syncthreads();
    }

    #pragma unroll
    for (int i = 0; i < 8; i++) {
        int ri = (i < 4) ? (ty * 4 + i) : (64 + ty * 4 + i - 4);
        int r = by * 128 + ri;
        #pragma unroll
        for (int j = 0; j < 8; j++) {
            int ci = (j < 4) ? (tx * 4 + j) : (64 + tx * 4 + j - 4);
            int cc = bx * 128 + ci;
            float v = acc[i][j];
            size_t oidx = (size_t)r * N + cc;
            if (EPI == 1) {
                v += bias[cc] + res[oidx];
            } else if (EPI == 2) {
                v += bias[cc];
                v = 0.5f * v * (1.0f + erff(v * 0.70710678118654752f));
            }
            out[oidx] = v;
        }
    }
}

// ---------------- attention: one block per (window, head) --------------------
// K,V tiles in dynamic smem; each thread owns one query row; online softmax.
__global__ void attn_kernel(const float* __restrict__ qkv, float* __restrict__ out)
{
    extern __shared__ float sm[];
    float* Ks = sm;                // [196*32]
    float* Vs = sm + NTOKW * DHEAD;

    int blk = blockIdx.x;          // 0..3071
    int win = blk / HEADS;
    int head = blk - win * HEADS;
    int b = win / WIN_PER_B;
    int wr = win - b * WIN_PER_B;
    int wh = wr / NWIN_SIDE;
    int ww = wr - wh * NWIN_SIDE;
    int h0 = wh * WS, w0 = ww * WS;
    int tid = threadIdx.x;

    // cooperative load of K and V for this window/head
    for (int idx = tid; idx < NTOKW * DHEAD; idx += blockDim.x) {
        int j = idx >> 5;
        int e = idx & 31;
        int tok = b * HW + (h0 + j / WS) * WW + (w0 + j % WS);
        size_t off = (size_t)tok * QKV_DIM + head * DHEAD + e;
        Ks[idx] = qkv[off + C];
        Vs[idx] = qkv[off + 2 * C];
    }
    __syncthreads();

    if (tid < NTOKW) {
        const float scale = 0.17677669529663687f; // 32^-0.5
        int tok = b * HW + (h0 + tid / WS) * WW + (w0 + tid % WS);
        const float* qp = qkv + (size_t)tok * QKV_DIM + head * DHEAD;
        float q[DHEAD];
        #pragma unroll
        for (int e = 0; e < DHEAD; e++) q[e] = qp[e] * scale;

        float m = -1e30f, l = 0.f;
        float acc[DHEAD];
        #pragma unroll
        for (int e = 0; e < DHEAD; e++) acc[e] = 0.f;

        for (int j = 0; j < NTOKW; j++) {
            const float* kr = Ks + j * DHEAD;
            float s = 0.f;
            #pragma unroll
            for (int e = 0; e < DHEAD; e++) s = fmaf(q[e], kr[e], s);
            float mn = fmaxf(m, s);
            float co = __expf(m - mn);
            float p  = __expf(s - mn);
            l = l * co + p;
            const float* vr = Vs + j * DHEAD;
            #pragma unroll
            for (int e = 0; e < DHEAD; e++)
                acc[e] = fmaf(acc[e], co, p * vr[e]);
            m = mn;
        }
        float inv = 1.f / l;
        float* op = out + (size_t)tok * C + head * DHEAD;
        #pragma unroll
        for (int e = 0; e < DHEAD; e++) op[e] = acc[e] * inv;
    }
}

// ---------------- final transpose BHWC -> BCHW -------------------------------
__global__ void transpose_kernel(const float* __restrict__ in, float* __restrict__ out)
{
    __shared__ float tile[32][33];
    int b = blockIdx.z;
    int hw0 = blockIdx.x * 32;
    int c0 = blockIdx.y * 32;
    int txx = threadIdx.x;

    for (int r = threadIdx.y; r < 32; r += 8) {
        tile[r][txx] = in[((size_t)b * HW + hw0 + r) * C + c0 + txx];
    }
    __syncthreads();
    for (int r = threadIdx.y; r < 32; r += 8) {
        out[((size_t)b * C + c0 + r) * HW + hw0 + txx] = tile[txx][r];
    }
}

// ---------------- launcher ---------------------------------------------------
extern "C" void kernel_launch(void* const* d_in, const int* in_sizes, int n_in,
                              void* d_out, int out_size)
{
    const float* x      = (const float*)d_in[0];
    const float* conv_w = (const float*)d_in[1];
    const float* conv_b = (const float*)d_in[2];
    const float* ln1_w  = (const float*)d_in[3];
    const float* ln1_b  = (const float*)d_in[4];
    const float* qkv_w  = (const float*)d_in[5];
    const float* proj_w = (const float*)d_in[6];
    const float* proj_b = (const float*)d_in[7];
    const float* ln2_w  = (const float*)d_in[8];
    const float* ln2_b  = (const float*)d_in[9];
    const float* fc1_w  = (const float*)d_in[10];
    const float* fc1_b  = (const float*)d_in[11];
    const float* fc2_w  = (const float*)d_in[12];
    const float* fc2_b  = (const float*)d_in[13];
    float* out = (float*)d_out;

    float *p_x1, *p_xn, *p_qkv, *p_attn, *p_x2, *p_h, *p_x3;
    cudaGetSymbolAddress((void**)&p_x1, g_x1);
    cudaGetSymbolAddress((void**)&p_xn, g_xn);
    cudaGetSymbolAddress((void**)&p_qkv, g_qkv);
    cudaGetSymbolAddress((void**)&p_attn, g_attn);
    cudaGetSymbolAddress((void**)&p_x2, g_x2);
    cudaGetSymbolAddress((void**)&p_h, g_h);
    cudaGetSymbolAddress((void**)&p_x3, g_x3);

    int attn_smem = NTOKW * DHEAD * 2 * sizeof(float);  // 50176 B
    cudaFuncSetAttribute(attn_kernel, cudaFuncAttributeMaxDynamicSharedMemorySize, attn_smem);

    // 1. depthwise conv + bias + residual -> BHWC
    conv_pe_kernel<<<NTOK, C>>>(x, conv_w, conv_b, p_x1);

    // 2. LN1
    ln_kernel<<<NTOK, 128>>>(p_x1, ln1_w, ln1_b, p_xn);

    // 3. QKV gemm: [NTOK,384] @ [1152,384]^T
    sgemm_kernel<0><<<dim3(QKV_DIM / 128, NTOK / 128), 256>>>(
        p_xn, qkv_w, nullptr, nullptr, p_qkv, NTOK, QKV_DIM, C);

    // 4. windowed attention
    attn_kernel<<<NWIN * HEADS, 256, attn_smem>>>(p_qkv, p_attn);

    // 5. proj gemm + bias + residual(x1)
    sgemm_kernel<1><<<dim3(C / 128, NTOK / 128), 256>>>(
        p_attn, proj_w, proj_b, p_x1, p_x2, NTOK, C, C);

    // 6. LN2
    ln_kernel<<<NTOK, 128>>>(p_x2, ln2_w, ln2_b, p_xn);

    // 7. fc1 gemm + bias + GELU
    sgemm_kernel<2><<<dim3(MLP_HID / 128, NTOK / 128), 256>>>(
        p_xn, fc1_w, fc1_b, nullptr, p_h, NTOK, MLP_HID, C);

    // 8. fc2 gemm + bias + residual(x2)
    sgemm_kernel<1><<<dim3(C / 128, NTOK / 128), 256>>>(
        p_h, fc2_w, fc2_b, p_x2, p_x3, NTOK, C, MLP_HID);

    // 9. BHWC -> BCHW
    transpose_kernel<<<dim3(HW / 32, C / 32, BATCH), dim3(32, 8)>>>(p_x3, out);
}

// round 2
// speedup vs baseline: 1.5665x; 1.5665x over previous
#include <cuda_runtime.h>
#include <cuda_bf16.h>
#include <math.h>
#include <stdint.h>

// Problem constants
#define BATCH 16
#define C 384
#define HH 56
#define WW 56
#define HW (HH*WW)            // 3136
#define NTOK (BATCH*HW)       // 50176
#define HEADS 12
#define DHEAD 32
#define WS 14
#define NWIN_SIDE 4           // 56/14
#define WIN_PER_B 16
#define NWIN (BATCH*WIN_PER_B) // 256
#define NTOKW (WS*WS)          // 196
#define MLP_HID (4*C)          // 1536
#define QKV_DIM (3*C)          // 1152

// ---------------- scratch buffers (device globals; no runtime allocation) ----
__device__ float g_x1[(size_t)NTOK * C];       // conv+residual output (BHWC), attention shortcut
__device__ float g_xn[(size_t)NTOK * C];       // LN output (reused for LN1 and LN2)
__device__ float g_qkv[(size_t)NTOK * QKV_DIM];
__device__ float g_attn[(size_t)NTOK * C];
__device__ float g_x2[(size_t)NTOK * C];       // after proj + residual
__device__ float g_h[(size_t)NTOK * MLP_HID];  // MLP hidden
__device__ float g_x3[(size_t)NTOK * C];       // final BHWC before transpose

// ---------------- kernel 1: depthwise 3x3 conv + bias + residual, NCHW -> BHWC
__global__ void conv_pe_kernel(const float* __restrict__ x,
                               const float* __restrict__ cw,
                               const float* __restrict__ cb,
                               float* __restrict__ out)
{
    int pix = blockIdx.x;            // b*HW + h*W + w
    int c = threadIdx.x;             // 0..383
    int b = pix / HW;
    int hw = pix - b * HW;
    int h = hw / WW;
    int w = hw - h * WW;

    const float* xc = x + ((size_t)(b * C + c)) * HW;
    const float* wc = cw + c * 9;

    float s = cb[c] + xc[h * WW + w];   // bias + residual
    #pragma unroll
    for (int dy = -1; dy <= 1; dy++) {
        int hh = h + dy;
        if (hh < 0 || hh >= HH) continue;
        #pragma unroll
        for (int dx = -1; dx <= 1; dx++) {
            int ww = w + dx;
            if (ww < 0 || ww >= WW) continue;
            s += xc[hh * WW + ww] * wc[(dy + 1) * 3 + (dx + 1)];
        }
    }
    out[(size_t)pix * C + c] = s;
}

// ---------------- layer norm over C=384 (one block per token, 128 threads) ---
__global__ void ln_kernel(const float* __restrict__ x,
                          const float* __restrict__ w,
                          const float* __restrict__ b,
                          float* __restrict__ y)
{
    __shared__ float red[4];
    int t = blockIdx.x;
    int tid = threadIdx.x;
    const float* xr = x + (size_t)t * C;

    float v0 = xr[tid];
    float v1 = xr[tid + 128];
    float v2 = xr[tid + 256];

    float s = v0 + v1 + v2;
    for (int o = 16; o > 0; o >>= 1) s += __shfl_down_sync(0xffffffffu, s, o);
    if ((tid & 31) == 0) red[tid >> 5] = s;
    __syncthreads();
    float tot = red[0] + red[1] + red[2] + red[3];
    float mean = tot * (1.0f / C);

    float d0 = v0 - mean, d1 = v1 - mean, d2 = v2 - mean;
    float q = d0 * d0 + d1 * d1 + d2 * d2;
    __syncthreads();
    for (int o = 16; o > 0; o >>= 1) q += __shfl_down_sync(0xffffffffu, q, o);
    if ((tid & 31) == 0) red[tid >> 5] = q;
    __syncthreads();
    float var = (red[0] + red[1] + red[2] + red[3]) * (1.0f / C);
    float rstd = rsqrtf(var + 1e-5f);

    float* yr = y + (size_t)t * C;
    yr[tid]       = d0 * rstd * w[tid]       + b[tid];
    yr[tid + 128] = d1 * rstd * w[tid + 128] + b[tid + 128];
    yr[tid + 256] = d2 * rstd * w[tid + 256] + b[tid + 256];
}

// ---------------- tf32 tensor-core GEMM ------------------------------------
// out[M,N] = A[M,K] @ W[N,K]^T (+bias)(+res)(+gelu)
// EPI: 0 = plain, 1 = +bias +residual, 2 = +bias then exact GELU
// 128x128x16 block tile, 8 warps, 32x64 warp tile of m16n8k8 mma.sync.

__device__ __forceinline__ uint32_t f2tf32(float f) {
    uint32_t r;
    asm("cvt.rna.tf32.f32 %0, %1;" : "=r"(r) : "f"(f));
    return r;
}

#define MMA_TF32(d, a, b)                                              \
    asm volatile(                                                      \
        "mma.sync.aligned.m16n8k8.row.col.f32.tf32.tf32.f32 "          \
        "{%0,%1,%2,%3},{%4,%5,%6,%7},{%8,%9},{%0,%1,%2,%3};\n"         \
        : "+f"(d[0]), "+f"(d[1]), "+f"(d[2]), "+f"(d[3])               \
        : "r"(a[0]), "r"(a[1]), "r"(a[2]), "r"(a[3]), "r"(b[0]), "r"(b[1]))

#define SM_STRIDE 136   // (stride*k) % 32 == 8*k -> conflict-free frag reads

template<int EPI>
__global__ void __launch_bounds__(256, 2)
tgemm_kernel(const float* __restrict__ A, const float* __restrict__ W,
             const float* __restrict__ bias, const float* __restrict__ res,
             float* __restrict__ out, int M, int N, int K)
{
    __shared__ uint32_t As[2][16][SM_STRIDE];
    __shared__ uint32_t Bs[2][16][SM_STRIDE];

    int tid = threadIdx.x;
    int lane = tid & 31, warp = tid >> 5;
    int warpM = (warp >> 1) * 32;   // 0,32,64,96
    int warpN = (warp & 1) * 64;    // 0,64
    int gid = lane >> 2;            // groupID 0..7
    int tig = lane & 3;             // thread-in-group

    int lrow = tid >> 1;            // 0..127 (tile row this thread loads)
    int lk   = (tid & 1) * 8;       // k offset 0 or 8
    const float* Ap = A + (size_t)(blockIdx.y * 128 + lrow) * K + lk;
    const float* Wp = W + (size_t)(blockIdx.x * 128 + lrow) * K + lk;

    float acc[2][8][4] = {};
    int nk = K >> 4;

    float4 ra0, ra1, rb0, rb1;

    // preload tile 0
    ra0 = *(const float4*)(Ap);     ra1 = *(const float4*)(Ap + 4);
    rb0 = *(const float4*)(Wp);     rb1 = *(const float4*)(Wp + 4);
    {
        As[0][lk+0][lrow] = f2tf32(ra0.x); As[0][lk+1][lrow] = f2tf32(ra0.y);
        As[0][lk+2][lrow] = f2tf32(ra0.z); As[0][lk+3][lrow] = f2tf32(ra0.w);
        As[0][lk+4][lrow] = f2tf32(ra1.x); As[0][lk+5][lrow] = f2tf32(ra1.y);
        As[0][lk+6][lrow] = f2tf32(ra1.z); As[0][lk+7][lrow] = f2tf32(ra1.w);
        Bs[0][lk+0][lrow] = f2tf32(rb0.x); Bs[0][lk+1][lrow] = f2tf32(rb0.y);
        Bs[0][lk+2][lrow] = f2tf32(rb0.z); Bs[0][lk+3][lrow] = f2tf32(rb0.w);
        Bs[0][lk+4][lrow] = f2tf32(rb1.x); Bs[0][lk+5][lrow] = f2tf32(rb1.y);
        Bs[0][lk+6][lrow] = f2tf32(rb1.z); Bs[0][lk+7][lrow] = f2tf32(rb1.w);
    }
    __syncthreads();

    for (int kt = 0; kt < nk; kt++) {
        int cur = kt & 1, nxt = cur ^ 1;
        if (kt + 1 < nk) {
            const float* Ap2 = Ap + (kt + 1) * 16;
            const float* Wp2 = Wp + (kt + 1) * 16;
            ra0 = *(const float4*)(Ap2);     ra1 = *(const float4*)(Ap2 + 4);
            rb0 = *(const float4*)(Wp2);     rb1 = *(const float4*)(Wp2 + 4);
        }

        #pragma unroll
        for (int ks = 0; ks < 2; ks++) {
            uint32_t af[2][4], bf[8][2];
            #pragma unroll
            for (int mt = 0; mt < 2; mt++) {
                int r = warpM + mt * 16 + gid;
                af[mt][0] = As[cur][ks*8 + tig    ][r];
                af[mt][1] = As[cur][ks*8 + tig    ][r + 8];
                af[mt][2] = As[cur][ks*8 + tig + 4][r];
                af[mt][3] = As[cur][ks*8 + tig + 4][r + 8];
            }
            #pragma unroll
            for (int nt = 0; nt < 8; nt++) {
                int cn = warpN + nt * 8 + gid;
                bf[nt][0] = Bs[cur][ks*8 + tig    ][cn];
                bf[nt][1] = Bs[cur][ks*8 + tig + 4][cn];
            }
            #pragma unroll
            for (int mt = 0; mt < 2; mt++)
                #pragma unroll
                for (int nt = 0; nt < 8; nt++)
                    MMA_TF32(acc[mt][nt], af[mt], bf[nt]);
        }

        if (kt + 1 < nk) {
            As[nxt][lk+0][lrow] = f2tf32(ra0.x); As[nxt][lk+1][lrow] = f2tf32(ra0.y);
            As[nxt][lk+2][lrow] = f2tf32(ra0.z); As[nxt][lk+3][lrow] = f2tf32(ra0.w);
            As[nxt][lk+4][lrow] = f2tf32(ra1.x); As[nxt][lk+5][lrow] = f2tf32(ra1.y);
            As[nxt][lk+6][lrow] = f2tf32(ra1.z); As[nxt][lk+7][lrow] = f2tf32(ra1.w);
            Bs[nxt][lk+0][lrow] = f2tf32(rb0.x); Bs[nxt][lk+1][lrow] = f2tf32(rb0.y);
            Bs[nxt][lk+2][lrow] = f2tf32(rb0.z); Bs[nxt][lk+3][lrow] = f2tf32(rb0.w);
            Bs[nxt][lk+4][lrow] = f2tf32(rb1.x); Bs[nxt][lk+5][lrow] = f2tf32(rb1.y);
            Bs[nxt][lk+6][lrow] = f2tf32(rb1.z); Bs[nxt][lk+7][lrow] = f2tf32(rb1.w);
        }
        __syncthreads();
    }

    // epilogue: c0,c1 -> row gid cols 2*tig,2*tig+1 ; c2,c3 -> row gid+8
    #pragma unroll
    for (int mt = 0; mt < 2; mt++) {
        #pragma unroll
        for (int half = 0; half < 2; half++) {
            int r = blockIdx.y * 128 + warpM + mt * 16 + gid + half * 8;
            #pragma unroll
            for (int nt = 0; nt < 8; nt++) {
                int cc = blockIdx.x * 128 + warpN + nt * 8 + 2 * tig;
                float v0 = acc[mt][nt][half * 2 + 0];
                float v1 = acc[mt][nt][half * 2 + 1];
                size_t oi = (size_t)r * N + cc;
                if (EPI == 1) {
                    v0 += bias[cc]     + res[oi];
                    v1 += bias[cc + 1] + res[oi + 1];
                } else if (EPI == 2) {
                    v0 += bias[cc];
                    v1 += bias[cc + 1];
                    v0 = 0.5f * v0 * (1.0f + erff(v0 * 0.70710678118654752f));
                    v1 = 0.5f * v1 * (1.0f + erff(v1 * 0.70710678118654752f));
                }
                out[oi]     = v0;
                out[oi + 1] = v1;
            }
        }
    }
}

// ---------------- attention: one block per (window, head) --------------------
__global__ void attn_kernel(const float* __restrict__ qkv, float* __restrict__ out)
{
    extern __shared__ float sm[];
    float* Ks = sm;                // [196*32]
    float* Vs = sm + NTOKW * DHEAD;

    int blk = blockIdx.x;          // 0..3071
    int win = blk / HEADS;
    int head = blk - win * HEADS;
    int b = win / WIN_PER_B;
    int wr = win - b * WIN_PER_B;
    int wh = wr / NWIN_SIDE;
    int ww = wr - wh * NWIN_SIDE;
    int h0 = wh * WS, w0 = ww * WS;
    int tid = threadIdx.x;

    for (int idx = tid; idx < NTOKW * DHEAD; idx += blockDim.x) {
        int j = idx >> 5;
        int e = idx & 31;
        int tok = b * HW + (h0 + j / WS) * WW + (w0 + j % WS);
        size_t off = (size_t)tok * QKV_DIM + head * DHEAD + e;
        Ks[idx] = qkv[off + C];
        Vs[idx] = qkv[off + 2 * C];
    }
    __syncthreads();

    if (tid < NTOKW) {
        const float scale = 0.17677669529663687f; // 32^-0.5
        int tok = b * HW + (h0 + tid / WS) * WW + (w0 + tid % WS);
        const float* qp = qkv + (size_t)tok * QKV_DIM + head * DHEAD;
        float q[DHEAD];
        #pragma unroll
        for (int e = 0; e < DHEAD; e++) q[e] = qp[e] * scale;

        float m = -1e30f, l = 0.f;
        float acc[DHEAD];
        #pragma unroll
        for (int e = 0; e < DHEAD; e++) acc[e] = 0.f;

        for (int j = 0; j < NTOKW; j++) {
            const float* kr = Ks + j * DHEAD;
            float s = 0.f;
            #pragma unroll
            for (int e = 0; e < DHEAD; e++) s = fmaf(q[e], kr[e], s);
            float mn = fmaxf(m, s);
            float co = __expf(m - mn);
            float p  = __expf(s - mn);
            l = l * co + p;
            const float* vr = Vs + j * DHEAD;
            #pragma unroll
            for (int e = 0; e < DHEAD; e++)
                acc[e] = fmaf(acc[e], co, p * vr[e]);
            m = mn;
        }
        float inv = 1.f / l;
        float* op = out + (size_t)tok * C + head * DHEAD;
        #pragma unroll
        for (int e = 0; e < DHEAD; e++) op[e] = acc[e] * inv;
    }
}

// ---------------- final transpose BHWC -> BCHW -------------------------------
__global__ void transpose_kernel(const float* __restrict__ in, float* __restrict__ out)
{
    __shared__ float tile[32][33];
    int b = blockIdx.z;
    int hw0 = blockIdx.x * 32;
    int c0 = blockIdx.y * 32;
    int txx = threadIdx.x;

    for (int r = threadIdx.y; r < 32; r += 8) {
        tile[r][txx] = in[((size_t)b * HW + hw0 + r) * C + c0 + txx];
    }
    __syncthreads();
    for (int r = threadIdx.y; r < 32; r += 8) {
        out[((size_t)b * C + c0 + r) * HW + hw0 + txx] = tile[txx][r];
    }
}

// ---------------- launcher ---------------------------------------------------
extern "C" void kernel_launch(void* const* d_in, const int* in_sizes, int n_in,
                              void* d_out, int out_size)
{
    const float* x      = (const float*)d_in[0];
    const float* conv_w = (const float*)d_in[1];
    const float* conv_b = (const float*)d_in[2];
    const float* ln1_w  = (const float*)d_in[3];
    const float* ln1_b  = (const float*)d_in[4];
    const float* qkv_w  = (const float*)d_in[5];
    const float* proj_w = (const float*)d_in[6];
    const float* proj_b = (const float*)d_in[7];
    const float* ln2_w  = (const float*)d_in[8];
    const float* ln2_b  = (const float*)d_in[9];
    const float* fc1_w  = (const float*)d_in[10];
    const float* fc1_b  = (const float*)d_in[11];
    const float* fc2_w  = (const float*)d_in[12];
    const float* fc2_b  = (const float*)d_in[13];
    float* out = (float*)d_out;

    float *p_x1, *p_xn, *p_qkv, *p_attn, *p_x2, *p_h, *p_x3;
    cudaGetSymbolAddress((void**)&p_x1, g_x1);
    cudaGetSymbolAddress((void**)&p_xn, g_xn);
    cudaGetSymbolAddress((void**)&p_qkv, g_qkv);
    cudaGetSymbolAddress((void**)&p_attn, g_attn);
    cudaGetSymbolAddress((void**)&p_x2, g_x2);
    cudaGetSymbolAddress((void**)&p_h, g_h);
    cudaGetSymbolAddress((void**)&p_x3, g_x3);

    int attn_smem = NTOKW * DHEAD * 2 * sizeof(float);  // 50176 B
    cudaFuncSetAttribute(attn_kernel, cudaFuncAttributeMaxDynamicSharedMemorySize, attn_smem);

    // 1. depthwise conv + bias + residual -> BHWC
    conv_pe_kernel<<<NTOK, C>>>(x, conv_w, conv_b, p_x1);

    // 2. LN1
    ln_kernel<<<NTOK, 128>>>(p_x1, ln1_w, ln1_b, p_xn);

    // 3. QKV gemm: [NTOK,384] @ [1152,384]^T
    tgemm_kernel<0><<<dim3(QKV_DIM / 128, NTOK / 128), 256>>>(
        p_xn, qkv_w, nullptr, nullptr, p_qkv, NTOK, QKV_DIM, C);

    // 4. windowed attention
    attn_kernel<<<NWIN * HEADS, 256, attn_smem>>>(p_qkv, p_attn);

    // 5. proj gemm + bias + residual(x1)
    tgemm_kernel<1><<<dim3(C / 128, NTOK / 128), 256>>>(
        p_attn, proj_w, proj_b, p_x1, p_x2, NTOK, C, C);

    // 6. LN2
    ln_kernel<<<NTOK, 128>>>(p_x2, ln2_w, ln2_b, p_xn);

    // 7. fc1 gemm + bias + GELU
    tgemm_kernel<2><<<dim3(MLP_HID / 128, NTOK / 128), 256>>>(
        p_xn, fc1_w, fc1_b, nullptr, p_h, NTOK, MLP_HID, C);

    // 8. fc2 gemm + bias + residual(x2)
    tgemm_kernel<1><<<dim3(C / 128, NTOK / 128), 256>>>(
        p_h, fc2_w, fc2_b, p_x2, p_x3, NTOK, C, MLP_HID);

    // 9. BHWC -> BCHW
    transpose_kernel<<<dim3(HW / 32, C / 32, BATCH), dim3(32, 8)>>>(p_x3, out);
}

// round 3
// speedup vs baseline: 3.1411x; 2.0052x over previous
#include <cuda_runtime.h>
#include <cuda_bf16.h>
#include <math.h>
#include <stdint.h>

// Problem constants
#define BATCH 16
#define C 384
#define HH 56
#define WW 56
#define HW (HH*WW)            // 3136
#define NTOK (BATCH*HW)       // 50176
#define HEADS 12
#define DHEAD 32
#define WS 14
#define NWIN_SIDE 4
#define WIN_PER_B 16
#define NWIN (BATCH*WIN_PER_B) // 256
#define NTOKW (WS*WS)          // 196
#define MLP_HID (4*C)          // 1536
#define QKV_DIM (3*C)          // 1152

// ---------------- scratch buffers -------------------------------------------
__device__ float g_x1[(size_t)NTOK * C];
__device__ float g_xn[(size_t)NTOK * C];
__device__ float g_qkv[(size_t)NTOK * QKV_DIM];
__device__ float g_attn[(size_t)NTOK * C];
__device__ float g_x2[(size_t)NTOK * C];
__device__ float g_h[(size_t)NTOK * MLP_HID];
__device__ float g_x3[(size_t)NTOK * C];
// tf32-rounded weight copies
__device__ float g_wq[(size_t)QKV_DIM * C];
__device__ float g_wp[(size_t)C * C];
__device__ float g_w1[(size_t)MLP_HID * C];
__device__ float g_w2[(size_t)C * MLP_HID];

__device__ __forceinline__ uint32_t f2tf32(float f) {
    uint32_t r;
    asm("cvt.rna.tf32.f32 %0, %1;" : "=r"(r) : "f"(f));
    return r;
}
__device__ __forceinline__ float tf32f(float f) { return __uint_as_float(f2tf32(f)); }

#define MMA_TF32(d, a, b)                                              \
    asm volatile(                                                      \
        "mma.sync.aligned.m16n8k8.row.col.f32.tf32.tf32.f32 "          \
        "{%0,%1,%2,%3},{%4,%5,%6,%7},{%8,%9},{%0,%1,%2,%3};\n"         \
        : "+f"(d[0]), "+f"(d[1]), "+f"(d[2]), "+f"(d[3])               \
        : "r"(a[0]), "r"(a[1]), "r"(a[2]), "r"(a[3]), "r"(b[0]), "r"(b[1]))

__device__ __forceinline__ void cpasync16(void* smem_dst, const void* gsrc) {
    uint32_t s = (uint32_t)__cvta_generic_to_shared(smem_dst);
    asm volatile("cp.async.cg.shared.global [%0], [%1], 16;" :: "r"(s), "l"(gsrc));
}

// ---------------- weight rounding to tf32 ------------------------------------
__global__ void round_tf32_kernel(const float* __restrict__ in, float* __restrict__ out, int n)
{
    int i = blockIdx.x * 256 + threadIdx.x;
    if (i < n) out[i] = tf32f(in[i]);
}

// ---------------- depthwise conv + bias + residual, NCHW -> BHWC -------------
__global__ void conv_pe_kernel(const float* __restrict__ x,
                               const float* __restrict__ cw,
                               const float* __restrict__ cb,
                               float* __restrict__ out)
{
    __shared__ float sx[3][58][33];
    int c0 = blockIdx.x * 32;
    int h  = blockIdx.y;
    int b  = blockIdx.z;
    int tid = threadIdx.x;

    for (int idx = tid; idx < 32 * 3 * 58; idx += 256) {
        int wq = idx % 58;
        int t  = idx / 58;
        int hh = t % 3;
        int c  = t / 3;
        int gh = h + hh - 1, gw = wq - 1;
        float v = 0.f;
        if (gh >= 0 && gh < HH && gw >= 0 && gw < WW)
            v = x[(size_t)(b * C + c0 + c) * HW + gh * WW + gw];
        sx[hh][wq][c] = v;
    }
    __syncthreads();

    for (int o = tid; o < 32 * WW; o += 256) {
        int c = o & 31, w = o >> 5;
        const float* wt = cw + (size_t)(c0 + c) * 9;
        float s = cb[c0 + c] + sx[1][w + 1][c];
        #pragma unroll
        for (int dy = 0; dy < 3; dy++)
            #pragma unroll
            for (int dx = 0; dx < 3; dx++)
                s += sx[dy][w + dx][c] * wt[dy * 3 + dx];
        out[(size_t)(b * HW + h * WW + w) * C + c0 + c] = s;
    }
}

// ---------------- layer norm over C=384 (stores tf32-rounded) ---------------
__global__ void ln_kernel(const float* __restrict__ x,
                          const float* __restrict__ w,
                          const float* __restrict__ b,
                          float* __restrict__ y)
{
    __shared__ float red[4];
    int t = blockIdx.x;
    int tid = threadIdx.x;
    const float* xr = x + (size_t)t * C;

    float v0 = xr[tid];
    float v1 = xr[tid + 128];
    float v2 = xr[tid + 256];

    float s = v0 + v1 + v2;
    for (int o = 16; o > 0; o >>= 1) s += __shfl_down_sync(0xffffffffu, s, o);
    if ((tid & 31) == 0) red[tid >> 5] = s;
    __syncthreads();
    float tot = red[0] + red[1] + red[2] + red[3];
    float mean = tot * (1.0f / C);

    float d0 = v0 - mean, d1 = v1 - mean, d2 = v2 - mean;
    float q = d0 * d0 + d1 * d1 + d2 * d2;
    __syncthreads();
    for (int o = 16; o > 0; o >>= 1) q += __shfl_down_sync(0xffffffffu, q, o);
    if ((tid & 31) == 0) red[tid >> 5] = q;
    __syncthreads();
    float var = (red[0] + red[1] + red[2] + red[3]) * (1.0f / C);
    float rstd = rsqrtf(var + 1e-5f);

    float* yr = y + (size_t)t * C;
    yr[tid]       = tf32f(d0 * rstd * w[tid]       + b[tid]);
    yr[tid + 128] = tf32f(d1 * rstd * w[tid + 128] + b[tid + 128]);
    yr[tid + 256] = tf32f(d2 * rstd * w[tid + 256] + b[tid + 256]);
}

// ---------------- tf32 tensor-core GEMM, cp.async 3-stage --------------------
// out[M,N] = A[M,K] @ W[N,K]^T ; EPI 0 plain, 1 +bias+res, 2 +bias+GELU(tf32 out)
// A and W must already hold tf32-representable values.
#define GST (128*36)   // floats per stage per matrix

template<int EPI>
__global__ void __launch_bounds__(256, 2)
tgemm_kernel(const float* __restrict__ A, const float* __restrict__ W,
             const float* __restrict__ bias, const float* __restrict__ res,
             float* __restrict__ out, int M, int N, int K)
{
    extern __shared__ float sm[];
    float* As = sm;            // [3][128][36]
    float* Bs = sm + 3 * GST;

    int tid = threadIdx.x;
    int lane = tid & 31, warp = tid >> 5;
    int warpM = (warp >> 1) * 32;
    int warpN = (warp & 1) * 64;
    int gid = lane >> 2, tig = lane & 3;

    const float* Abase = A + (size_t)(blockIdx.y * 128) * K;
    const float* Wbase = W + (size_t)(blockIdx.x * 128) * K;
    int nk = K >> 5;

    auto issue = [&](int kt) {
        int st = kt % 3;
        #pragma unroll
        for (int i = 0; i < 4; i++) {
            int chunk = i * 256 + tid;
            int row = chunk >> 3, kc = chunk & 7;
            cpasync16(As + st * GST + row * 36 + kc * 4,
                      Abase + (size_t)row * K + kt * 32 + kc * 4);
        }
        #pragma unroll
        for (int i = 0; i < 4; i++) {
            int chunk = i * 256 + tid;
            int row = chunk >> 3, kc = chunk & 7;
            cpasync16(Bs + st * GST + row * 36 + kc * 4,
                      Wbase + (size_t)row * K + kt * 32 + kc * 4);
        }
    };

    issue(0); asm volatile("cp.async.commit_group;");
    issue(1); asm volatile("cp.async.commit_group;");

    float acc[2][8][4] = {};

    for (int kt = 0; kt < nk; kt++) {
        asm volatile("cp.async.wait_group 1;");
        __syncthreads();
        if (kt + 2 < nk) issue(kt + 2);
        asm volatile("cp.async.commit_group;");

        const float* Ac = As + (kt % 3) * GST;
        const float* Bc = Bs + (kt % 3) * GST;

        #pragma unroll
        for (int ks = 0; ks < 4; ks++) {
            uint32_t af[2][4], bf[8][2];
            #pragma unroll
            for (int mt = 0; mt < 2; mt++) {
                int r = warpM + mt * 16 + gid;
                af[mt][0] = __float_as_uint(Ac[r * 36 + ks * 8 + tig]);
                af[mt][1] = __float_as_uint(Ac[(r + 8) * 36 + ks * 8 + tig]);
                af[mt][2] = __float_as_uint(Ac[r * 36 + ks * 8 + tig + 4]);
                af[mt][3] = __float_as_uint(Ac[(r + 8) * 36 + ks * 8 + tig + 4]);
            }
            #pragma unroll
            for (int nt = 0; nt < 8; nt++) {
                int cn = warpN + nt * 8 + gid;
                bf[nt][0] = __float_as_uint(Bc[cn * 36 + ks * 8 + tig]);
                bf[nt][1] = __float_as_uint(Bc[cn * 36 + ks * 8 + tig + 4]);
            }
            #pragma unroll
            for (int mt = 0; mt < 2; mt++)
                #pragma unroll
                for (int nt = 0; nt < 8; nt++)
                    MMA_TF32(acc[mt][nt], af[mt], bf[nt]);
        }
    }

    #pragma unroll
    for (int mt = 0; mt < 2; mt++) {
        #pragma unroll
        for (int half = 0; half < 2; half++) {
            int r = blockIdx.y * 128 + warpM + mt * 16 + gid + half * 8;
            #pragma unroll
            for (int nt = 0; nt < 8; nt++) {
                int cc = blockIdx.x * 128 + warpN + nt * 8 + 2 * tig;
                float v0 = acc[mt][nt][half * 2 + 0];
                float v1 = acc[mt][nt][half * 2 + 1];
                size_t oi = (size_t)r * N + cc;
                if (EPI == 1) {
                    v0 += bias[cc]     + res[oi];
                    v1 += bias[cc + 1] + res[oi + 1];
                } else if (EPI == 2) {
                    v0 += bias[cc];
                    v1 += bias[cc + 1];
                    v0 = 0.5f * v0 * (1.0f + erff(v0 * 0.70710678118654752f));
                    v1 = 0.5f * v1 * (1.0f + erff(v1 * 0.70710678118654752f));
                    v0 = tf32f(v0);
                    v1 = tf32f(v1);
                }
                out[oi]     = v0;
                out[oi + 1] = v1;
            }
        }
    }
}

// ---------------- tensor-core windowed attention -----------------------------
// block = one (window, head); 7 warps, each owns 2 m16 tiles (rows pad 224).
// Keys padded to 224, processed in 4 chunks of 56 (7 n-tiles). Flash-style.
#define AT_QS_STRIDE 232
#define AT_SM_FLOATS (2*32*AT_QS_STRIDE + 224*40)   // Qs + Ks + VB = 23808
#define AT_SMEM_BYTES (AT_SM_FLOATS*4)              // 95232

__global__ void __launch_bounds__(224, 2)
attn_mma_kernel(const float* __restrict__ qkv, float* __restrict__ outp)
{
    extern __shared__ float smf[];
    float* Qs = smf;                      // [32][232] k-major
    float* Ks = smf + 32 * AT_QS_STRIDE;  // [32][232]
    float* VB = smf + 2 * 32 * AT_QS_STRIDE; // [224][40]

    int blk = blockIdx.x;
    int win = blk / HEADS;
    int head = blk - win * HEADS;
    int b = win / WIN_PER_B;
    int wr = win - b * WIN_PER_B;
    int h0 = (wr / NWIN_SIDE) * WS, w0 = (wr % NWIN_SIDE) * WS;

    int tid = threadIdx.x;
    int lane = tid & 31, warp = tid >> 5;
    int gid = lane >> 2, tig = lane & 3;
    const float scale = 0.17677669529663687f;

    // load Q,K,V (one row per thread)
    {
        int r = tid;
        if (r < NTOKW) {
            int tok = b * HW + (h0 + r / WS) * WW + (w0 + r % WS);
            const float4* q4 = (const float4*)(qkv + (size_t)tok * QKV_DIM + head * DHEAD);
            const float4* k4 = (const float4*)(qkv + (size_t)tok * QKV_DIM + C + head * DHEAD);
            const float4* v4 = (const float4*)(qkv + (size_t)tok * QKV_DIM + 2 * C + head * DHEAD);
            #pragma unroll
            for (int i = 0; i < 8; i++) {
                float4 q = q4[i], k = k4[i], v = v4[i];
                Qs[(i * 4 + 0) * AT_QS_STRIDE + r] = tf32f(q.x * scale);
                Qs[(i * 4 + 1) * AT_QS_STRIDE + r] = tf32f(q.y * scale);
                Qs[(i * 4 + 2) * AT_QS_STRIDE + r] = tf32f(q.z * scale);
                Qs[(i * 4 + 3) * AT_QS_STRIDE + r] = tf32f(q.w * scale);
                Ks[(i * 4 + 0) * AT_QS_STRIDE + r] = tf32f(k.x);
                Ks[(i * 4 + 1) * AT_QS_STRIDE + r] = tf32f(k.y);
                Ks[(i * 4 + 2) * AT_QS_STRIDE + r] = tf32f(k.z);
                Ks[(i * 4 + 3) * AT_QS_STRIDE + r] = tf32f(k.w);
                ((float4*)(VB + r * 40))[i] =
                    make_float4(tf32f(v.x), tf32f(v.y), tf32f(v.z), tf32f(v.w));
            }
        } else {
            #pragma unroll
            for (int i = 0; i < 32; i++) {
                Qs[i * AT_QS_STRIDE + r] = 0.f;
                Ks[i * AT_QS_STRIDE + r] = 0.f;
            }
            float4 z = make_float4(0.f, 0.f, 0.f, 0.f);
            #pragma unroll
            for (int i = 0; i < 8; i++) ((float4*)(VB + r * 40))[i] = z;
        }
    }
    __syncthreads();

    float mS[2][2], lS[2][2];
    float O[2][4][4] = {};
    #pragma unroll
    for (int i = 0; i < 2; i++) { mS[i][0] = mS[i][1] = -1e30f; lS[i][0] = lS[i][1] = 0.f; }

    #pragma unroll 1
    for (int ch = 0; ch < 4; ch++) {
        float S[2][7][4] = {};
        // ---- S = Q K^T for this key chunk
        #pragma unroll
        for (int ks = 0; ks < 4; ks++) {
            uint32_t af[2][4];
            #pragma unroll
            for (int mt = 0; mt < 2; mt++) {
                int r = warp * 32 + mt * 16 + gid;
                af[mt][0] = __float_as_uint(Qs[(ks * 8 + tig) * AT_QS_STRIDE + r]);
                af[mt][1] = __float_as_uint(Qs[(ks * 8 + tig) * AT_QS_STRIDE + r + 8]);
                af[mt][2] = __float_as_uint(Qs[(ks * 8 + tig + 4) * AT_QS_STRIDE + r]);
                af[mt][3] = __float_as_uint(Qs[(ks * 8 + tig + 4) * AT_QS_STRIDE + r + 8]);
            }
            #pragma unroll
            for (int nt = 0; nt < 7; nt++) {
                int col = ch * 56 + nt * 8 + gid;
                uint32_t bf[2];
                bf[0] = __float_as_uint(Ks[(ks * 8 + tig) * AT_QS_STRIDE + col]);
                bf[1] = __float_as_uint(Ks[(ks * 8 + tig + 4) * AT_QS_STRIDE + col]);
                #pragma unroll
                for (int mt = 0; mt < 2; mt++)
                    MMA_TF32(S[mt][nt], af[mt], bf);
            }
        }
        // ---- mask padded key columns (only last chunk reaches >=196)
        if (ch == 3) {
            #pragma unroll
            for (int nt = 0; nt < 7; nt++) {
                int col0 = 168 + nt * 8 + 2 * tig;
                if (col0 >= NTOKW) {
                    #pragma unroll
                    for (int u = 0; u < 4; u++) { S[0][nt][u] = -1e30f; S[1][nt][u] = -1e30f; }
                }
            }
        }
        // ---- online softmax update
        #pragma unroll
        for (int mt = 0; mt < 2; mt++) {
            #pragma unroll
            for (int half = 0; half < 2; half++) {
                float mc = -1e30f;
                #pragma unroll
                for (int nt = 0; nt < 7; nt++)
                    mc = fmaxf(mc, fmaxf(S[mt][nt][half * 2], S[mt][nt][half * 2 + 1]));
                mc = fmaxf(mc, __shfl_xor_sync(0xffffffffu, mc, 1));
                mc = fmaxf(mc, __shfl_xor_sync(0xffffffffu, mc, 2));
                float mn = fmaxf(mS[mt][half], mc);
                float sc = __expf(mS[mt][half] - mn);
                float rs = 0.f;
                #pragma unroll
                for (int nt = 0; nt < 7; nt++) {
                    float p0 = __expf(S[mt][nt][half * 2]     - mn);
                    float p1 = __expf(S[mt][nt][half * 2 + 1] - mn);
                    S[mt][nt][half * 2]     = p0;
                    S[mt][nt][half * 2 + 1] = p1;
                    rs += p0 + p1;
                }
                rs += __shfl_xor_sync(0xffffffffu, rs, 1);
                rs += __shfl_xor_sync(0xffffffffu, rs, 2);
                lS[mt][half] = lS[mt][half] * sc + rs;
                mS[mt][half] = mn;
                #pragma unroll
                for (int nv = 0; nv < 4; nv++) {
                    O[mt][nv][half * 2]     *= sc;
                    O[mt][nv][half * 2 + 1] *= sc;
                }
            }
        }
        // ---- O += P V  (re-fragment P from accumulator layout via shuffles)
        #pragma unroll
        for (int kt = 0; kt < 7; kt++) {
            uint32_t a[2][4];
            int src1 = (lane & ~3) | (tig >> 1);
            int src2 = src1 + 2;
            bool odd = (tig & 1);
            #pragma unroll
            for (int mt = 0; mt < 2; mt++) {
                float c0 = S[mt][kt][0], c1 = S[mt][kt][1];
                float c2 = S[mt][kt][2], c3 = S[mt][kt][3];
                float y0 = __shfl_sync(0xffffffffu, c0, src1);
                float y1 = __shfl_sync(0xffffffffu, c1, src1);
                float y2 = __shfl_sync(0xffffffffu, c0, src2);
                float y3 = __shfl_sync(0xffffffffu, c1, src2);
                float z0 = __shfl_sync(0xffffffffu, c2, src1);
                float z1 = __shfl_sync(0xffffffffu, c3, src1);
                float z2 = __shfl_sync(0xffffffffu, c2, src2);
                float z3 = __shfl_sync(0xffffffffu, c3, src2);
                a[mt][0] = __float_as_uint(odd ? y1 : y0);
                a[mt][2] = __float_as_uint(odd ? y3 : y2);
                a[mt][1] = __float_as_uint(odd ? z1 : z0);
                a[mt][3] = __float_as_uint(odd ? z3 : z2);
            }
            int key = ch * 56 + kt * 8;
            #pragma unroll
            for (int nv = 0; nv < 4; nv++) {
                uint32_t bf[2];
                bf[0] = __float_as_uint(VB[(key + tig) * 40 + nv * 8 + gid]);
                bf[1] = __float_as_uint(VB[(key + tig + 4) * 40 + nv * 8 + gid]);
                #pragma unroll
                for (int mt = 0; mt < 2; mt++)
                    MMA_TF32(O[mt][nv], a[mt], bf);
            }
        }
    }

    // ---- write output (tf32-rounded; feeds proj GEMM)
    #pragma unroll
    for (int mt = 0; mt < 2; mt++) {
        #pragma unroll
        for (int half = 0; half < 2; half++) {
            int r = warp * 32 + mt * 16 + gid + half * 8;
            if (r < NTOKW) {
                int tok = b * HW + (h0 + r / WS) * WW + (w0 + r % WS);
                float inv = 1.f / lS[mt][half];
                float* op = outp + (size_t)tok * C + head * DHEAD;
                #pragma unroll
                for (int nv = 0; nv < 4; nv++) {
                    int cb2 = nv * 8 + 2 * tig;
                    op[cb2]     = tf32f(O[mt][nv][half * 2]     * inv);
                    op[cb2 + 1] = tf32f(O[mt][nv][half * 2 + 1] * inv);
                }
            }
        }
    }
}

// ---------------- final transpose BHWC -> BCHW -------------------------------
__global__ void transpose_kernel(const float* __restrict__ in, float* __restrict__ out)
{
    __shared__ float tile[32][33];
    int b = blockIdx.z;
    int hw0 = blockIdx.x * 32;
    int c0 = blockIdx.y * 32;
    int txx = threadIdx.x;

    for (int r = threadIdx.y; r < 32; r += 8)
        tile[r][txx] = in[((size_t)b * HW + hw0 + r) * C + c0 + txx];
    __syncthreads();
    for (int r = threadIdx.y; r < 32; r += 8)
        out[((size_t)b * C + c0 + r) * HW + hw0 + txx] = tile[txx][r];
}

// ---------------- launcher ---------------------------------------------------
extern "C" void kernel_launch(void* const* d_in, const int* in_sizes, int n_in,
                              void* d_out, int out_size)
{
    const float* x      = (const float*)d_in[0];
    const float* conv_w = (const float*)d_in[1];
    const float* conv_b = (const float*)d_in[2];
    const float* ln1_w  = (const float*)d_in[3];
    const float* ln1_b  = (const float*)d_in[4];
    const float* qkv_w  = (const float*)d_in[5];
    const float* proj_w = (const float*)d_in[6];
    const float* proj_b = (const float*)d_in[7];
    const float* ln2_w  = (const float*)d_in[8];
    const float* ln2_b  = (const float*)d_in[9];
    const float* fc1_w  = (const float*)d_in[10];
    const float* fc1_b  = (const float*)d_in[11];
    const float* fc2_w  = (const float*)d_in[12];
    const float* fc2_b  = (const float*)d_in[13];
    float* out = (float*)d_out;

    float *p_x1, *p_xn, *p_qkv, *p_attn, *p_x2, *p_h, *p_x3;
    float *p_wq, *p_wp, *p_w1, *p_w2;
    cudaGetSymbolAddress((void**)&p_x1, g_x1);
    cudaGetSymbolAddress((void**)&p_xn, g_xn);
    cudaGetSymbolAddress((void**)&p_qkv, g_qkv);
    cudaGetSymbolAddress((void**)&p_attn, g_attn);
    cudaGetSymbolAddress((void**)&p_x2, g_x2);
    cudaGetSymbolAddress((void**)&p_h, g_h);
    cudaGetSymbolAddress((void**)&p_x3, g_x3);
    cudaGetSymbolAddress((void**)&p_wq, g_wq);
    cudaGetSymbolAddress((void**)&p_wp, g_wp);
    cudaGetSymbolAddress((void**)&p_w1, g_w1);
    cudaGetSymbolAddress((void**)&p_w2, g_w2);

    const int gemm_smem = 2 * 3 * GST * sizeof(float);   // 110592
    cudaFuncSetAttribute(tgemm_kernel<0>, cudaFuncAttributeMaxDynamicSharedMemorySize, gemm_smem);
    cudaFuncSetAttribute(tgemm_kernel<1>, cudaFuncAttributeMaxDynamicSharedMemorySize, gemm_smem);
    cudaFuncSetAttribute(tgemm_kernel<2>, cudaFuncAttributeMaxDynamicSharedMemorySize, gemm_smem);
    cudaFuncSetAttribute(attn_mma_kernel, cudaFuncAttributeMaxDynamicSharedMemorySize, AT_SMEM_BYTES);

    // 0. round weights to tf32 once per replay
    round_tf32_kernel<<<(QKV_DIM * C + 255) / 256, 256>>>(qkv_w, p_wq, QKV_DIM * C);
    round_tf32_kernel<<<(C * C + 255) / 256, 256>>>(proj_w, p_wp, C * C);
    round_tf32_kernel<<<(MLP_HID * C + 255) / 256, 256>>>(fc1_w, p_w1, MLP_HID * C);
    round_tf32_kernel<<<(C * MLP_HID + 255) / 256, 256>>>(fc2_w, p_w2, C * MLP_HID);

    // 1. depthwise conv + bias + residual -> BHWC
    conv_pe_kernel<<<dim3(C / 32, HH, BATCH), 256>>>(x, conv_w, conv_b, p_x1);

    // 2. LN1 (tf32-rounded out)
    ln_kernel<<<NTOK, 128>>>(p_x1, ln1_w, ln1_b, p_xn);

    // 3. QKV gemm
    tgemm_kernel<0><<<dim3(QKV_DIM / 128, NTOK / 128), 256, gemm_smem>>>(
        p_xn, p_wq, nullptr, nullptr, p_qkv, NTOK, QKV_DIM, C);

    // 4. windowed attention (tensor cores)
    attn_mma_kernel<<<NWIN * HEADS, 224, AT_SMEM_BYTES>>>(p_qkv, p_attn);

    // 5. proj gemm + bias + residual(x1)
    tgemm_kernel<1><<<dim3(C / 128, NTOK / 128), 256, gemm_smem>>>(
        p_attn, p_wp, proj_b, p_x1, p_x2, NTOK, C, C);

    // 6. LN2
    ln_kernel<<<NTOK, 128>>>(p_x2, ln2_w, ln2_b, p_xn);

    // 7. fc1 gemm + bias + GELU (tf32-rounded out)
    tgemm_kernel<2><<<dim3(MLP_HID / 128, NTOK / 128), 256, gemm_smem>>>(
        p_xn, p_w1, fc1_b, nullptr, p_h, NTOK, MLP_HID, C);

    // 8. fc2 gemm + bias + residual(x2)
    tgemm_kernel<1><<<dim3(C / 128, NTOK / 128), 256, gemm_smem>>>(
        p_h, p_w2, fc2_b, p_x2, p_x3, NTOK, C, MLP_HID);

    // 9. BHWC -> BCHW
    transpose_kernel<<<dim3(HW / 32, C / 32, BATCH), dim3(32, 8)>>>(p_x3, out);
}

// round 4
// speedup vs baseline: 4.5460x; 1.4473x over previous
#include <cuda_runtime.h>
#include <cuda_fp16.h>
#include <math.h>
#include <stdint.h>

// Problem constants
#define BATCH 16
#define C 384
#define HH 56
#define WW 56
#define HW (HH*WW)            // 3136
#define NTOK (BATCH*HW)       // 50176
#define HEADS 12
#define DHEAD 32
#define WS 14
#define NWIN_SIDE 4
#define WIN_PER_B 16
#define NWIN (BATCH*WIN_PER_B) // 256
#define NTOKW (WS*WS)          // 196
#define MLP_HID (4*C)          // 1536
#define QKV_DIM (3*C)          // 1152

// ---------------- scratch buffers -------------------------------------------
__device__ float  g_x1[(size_t)NTOK * C];        // residual stream fp32
__device__ float  g_x2[(size_t)NTOK * C];
__device__ float  g_x3[(size_t)NTOK * C];
__device__ __half g_xn[(size_t)NTOK * C];        // LN out (half)
__device__ __half g_qkv[(size_t)NTOK * QKV_DIM];
__device__ __half g_attn[(size_t)NTOK * C];
__device__ __half g_h[(size_t)NTOK * MLP_HID];
// half weight copies
__device__ __half g_wq[(size_t)QKV_DIM * C];
__device__ __half g_wp[(size_t)C * C];
__device__ __half g_w1[(size_t)MLP_HID * C];
__device__ __half g_w2[(size_t)C * MLP_HID];

__device__ __forceinline__ uint32_t pack_h2(float a, float b) {
    __half2 h = __floats2half2_rn(a, b);
    return *reinterpret_cast<uint32_t*>(&h);
}

#define MMA_F16_K16(d, a, b)                                           \
    asm volatile(                                                      \
        "mma.sync.aligned.m16n8k16.row.col.f32.f16.f16.f32 "           \
        "{%0,%1,%2,%3},{%4,%5,%6,%7},{%8,%9},{%0,%1,%2,%3};\n"         \
        : "+f"(d[0]), "+f"(d[1]), "+f"(d[2]), "+f"(d[3])               \
        : "r"(a[0]), "r"(a[1]), "r"(a[2]), "r"(a[3]), "r"(b[0]), "r"(b[1]))

#define MMA_F16_K8(d, a, b0)                                           \
    asm volatile(                                                      \
        "mma.sync.aligned.m16n8k8.row.col.f32.f16.f16.f32 "            \
        "{%0,%1,%2,%3},{%4,%5},{%6},{%0,%1,%2,%3};\n"                  \
        : "+f"(d[0]), "+f"(d[1]), "+f"(d[2]), "+f"(d[3])               \
        : "r"(a[0]), "r"(a[1]), "r"(b0))

__device__ __forceinline__ void cpasync8(void* smem_dst, const void* gsrc) {
    uint32_t s = (uint32_t)__cvta_generic_to_shared(smem_dst);
    asm volatile("cp.async.ca.shared.global [%0], [%1], 8;" :: "r"(s), "l"(gsrc));
}

// ---------------- weight conversion fp32 -> fp16 (single kernel) -------------
#define SQ (QKV_DIM*C)       // 442368
#define SP (C*C)             // 147456
#define S1 (MLP_HID*C)       // 589824
#define S2 (C*MLP_HID)       // 589824
__global__ void cvt_weights_kernel(const float* __restrict__ wq, const float* __restrict__ wp,
                                   const float* __restrict__ w1, const float* __restrict__ w2,
                                   __half* oq, __half* op_, __half* o1, __half* o2)
{
    int i = blockIdx.x * 256 + threadIdx.x;
    if (i < SQ) oq[i] = __float2half(wq[i]);
    else if (i < SQ + SP) op_[i - SQ] = __float2half(wp[i - SQ]);
    else if (i < SQ + SP + S1) o1[i - SQ - SP] = __float2half(w1[i - SQ - SP]);
    else if (i < SQ + SP + S1 + S2) o2[i - SQ - SP - S1] = __float2half(w2[i - SQ - SP - S1]);
}

// ---------------- depthwise conv + bias + residual, NCHW -> BHWC -------------
__global__ void conv_pe_kernel(const float* __restrict__ x,
                               const float* __restrict__ cw,
                               const float* __restrict__ cb,
                               float* __restrict__ out)
{
    __shared__ float sx[3][58][33];
    int c0 = blockIdx.x * 32;
    int h  = blockIdx.y;
    int b  = blockIdx.z;
    int tid = threadIdx.x;

    for (int idx = tid; idx < 32 * 3 * 58; idx += 256) {
        int wq = idx % 58;
        int t  = idx / 58;
        int hh = t % 3;
        int c  = t / 3;
        int gh = h + hh - 1, gw = wq - 1;
        float v = 0.f;
        if (gh >= 0 && gh < HH && gw >= 0 && gw < WW)
            v = x[(size_t)(b * C + c0 + c) * HW + gh * WW + gw];
        sx[hh][wq][c] = v;
    }
    __syncthreads();

    for (int o = tid; o < 32 * WW; o += 256) {
        int c = o & 31, w = o >> 5;
        const float* wt = cw + (size_t)(c0 + c) * 9;
        float s = cb[c0 + c] + sx[1][w + 1][c];
        #pragma unroll
        for (int dy = 0; dy < 3; dy++)
            #pragma unroll
            for (int dx = 0; dx < 3; dx++)
                s += sx[dy][w + dx][c] * wt[dy * 3 + dx];
        out[(size_t)(b * HW + h * WW + w) * C + c0 + c] = s;
    }
}

// ---------------- layer norm over C=384, half output -------------------------
__global__ void ln_kernel(const float* __restrict__ x,
                          const float* __restrict__ w,
                          const float* __restrict__ b,
                          __half* __restrict__ y)
{
    __shared__ float red[4];
    int t = blockIdx.x;
    int tid = threadIdx.x;
    const float* xr = x + (size_t)t * C;

    float v0 = xr[tid];
    float v1 = xr[tid + 128];
    float v2 = xr[tid + 256];

    float s = v0 + v1 + v2;
    for (int o = 16; o > 0; o >>= 1) s += __shfl_down_sync(0xffffffffu, s, o);
    if ((tid & 31) == 0) red[tid >> 5] = s;
    __syncthreads();
    float tot = red[0] + red[1] + red[2] + red[3];
    float mean = tot * (1.0f / C);

    float d0 = v0 - mean, d1 = v1 - mean, d2 = v2 - mean;
    float q = d0 * d0 + d1 * d1 + d2 * d2;
    __syncthreads();
    for (int o = 16; o > 0; o >>= 1) q += __shfl_down_sync(0xffffffffu, q, o);
    if ((tid & 31) == 0) red[tid >> 5] = q;
    __syncthreads();
    float var = (red[0] + red[1] + red[2] + red[3]) * (1.0f / C);
    float rstd = rsqrtf(var + 1e-5f);

    __half* yr = y + (size_t)t * C;
    yr[tid]       = __float2half(d0 * rstd * w[tid]       + b[tid]);
    yr[tid + 128] = __float2half(d1 * rstd * w[tid + 128] + b[tid + 128]);
    yr[tid + 256] = __float2half(d2 * rstd * w[tid + 256] + b[tid + 256]);
}

// ---------------- fp16 tensor-core GEMM, cp.async 3-stage --------------------
// out[M,N] = A[M,K] @ W[N,K]^T ; A,W half. EPI 0 plain->half, 1 +bias+res->f32,
// 2 +bias+GELU->half. 128x128x32 tile, 8 warps, smem [row][40] halves.
#define HST (128*40)   // halves per stage per matrix

template<int EPI>
__global__ void __launch_bounds__(256, 2)
hgemm_kernel(const __half* __restrict__ A, const __half* __restrict__ W,
             const float* __restrict__ bias, const float* __restrict__ res,
             void* __restrict__ outv, int M, int N, int K)
{
    extern __shared__ __half smh[];
    __half* As = smh;            // [3][128][40]
    __half* Bs = smh + 3 * HST;

    int tid = threadIdx.x;
    int lane = tid & 31, warp = tid >> 5;
    int warpM = (warp >> 1) * 32;
    int warpN = (warp & 1) * 64;
    int gid = lane >> 2, tig = lane & 3;

    const __half* Abase = A + (size_t)(blockIdx.y * 128) * K;
    const __half* Wbase = W + (size_t)(blockIdx.x * 128) * K;
    int nk = K >> 5;

    auto issue = [&](int kt) {
        int st = kt % 3;
        #pragma unroll
        for (int i = 0; i < 4; i++) {
            int chunk = i * 256 + tid;           // 0..1023
            int row = chunk >> 3, kc = chunk & 7;
            cpasync8(As + st * HST + row * 40 + kc * 4,
                     Abase + (size_t)row * K + kt * 32 + kc * 4);
        }
        #pragma unroll
        for (int i = 0; i < 4; i++) {
            int chunk = i * 256 + tid;
            int row = chunk >> 3, kc = chunk & 7;
            cpasync8(Bs + st * HST + row * 40 + kc * 4,
                     Wbase + (size_t)row * K + kt * 32 + kc * 4);
        }
    };

    issue(0); asm volatile("cp.async.commit_group;");
    issue(1); asm volatile("cp.async.commit_group;");

    float acc[2][8][4] = {};

    for (int kt = 0; kt < nk; kt++) {
        asm volatile("cp.async.wait_group 1;");
        __syncthreads();
        if (kt + 2 < nk) issue(kt + 2);
        asm volatile("cp.async.commit_group;");

        const __half* Ac = As + (kt % 3) * HST;
        const __half* Bc = Bs + (kt % 3) * HST;

        #pragma unroll
        for (int ks = 0; ks < 2; ks++) {
            uint32_t af[2][4], bf[8][2];
            #pragma unroll
            for (int mt = 0; mt < 2; mt++) {
                int r = warpM + mt * 16 + gid;
                af[mt][0] = *(const uint32_t*)(Ac + r * 40 + ks * 16 + 2 * tig);
                af[mt][1] = *(const uint32_t*)(Ac + (r + 8) * 40 + ks * 16 + 2 * tig);
                af[mt][2] = *(const uint32_t*)(Ac + r * 40 + ks * 16 + 2 * tig + 8);
                af[mt][3] = *(const uint32_t*)(Ac + (r + 8) * 40 + ks * 16 + 2 * tig + 8);
            }
            #pragma unroll
            for (int nt = 0; nt < 8; nt++) {
                int cn = warpN + nt * 8 + gid;
                bf[nt][0] = *(const uint32_t*)(Bc + cn * 40 + ks * 16 + 2 * tig);
                bf[nt][1] = *(const uint32_t*)(Bc + cn * 40 + ks * 16 + 2 * tig + 8);
            }
            #pragma unroll
            for (int mt = 0; mt < 2; mt++)
                #pragma unroll
                for (int nt = 0; nt < 8; nt++)
                    MMA_F16_K16(acc[mt][nt], af[mt], bf[nt]);
        }
    }

    #pragma unroll
    for (int mt = 0; mt < 2; mt++) {
        #pragma unroll
        for (int half = 0; half < 2; half++) {
            int r = blockIdx.y * 128 + warpM + mt * 16 + gid + half * 8;
            #pragma unroll
            for (int nt = 0; nt < 8; nt++) {
                int cc = blockIdx.x * 128 + warpN + nt * 8 + 2 * tig;
                float v0 = acc[mt][nt][half * 2 + 0];
                float v1 = acc[mt][nt][half * 2 + 1];
                size_t oi = (size_t)r * N + cc;
                if (EPI == 1) {
                    v0 += bias[cc]     + res[oi];
                    v1 += bias[cc + 1] + res[oi + 1];
                    ((float*)outv)[oi]     = v0;
                    ((float*)outv)[oi + 1] = v1;
                } else {
                    if (EPI == 2) {
                        v0 += bias[cc];
                        v1 += bias[cc + 1];
                        v0 = 0.5f * v0 * (1.0f + erff(v0 * 0.70710678118654752f));
                        v1 = 0.5f * v1 * (1.0f + erff(v1 * 0.70710678118654752f));
                    }
                    *(__half2*)((__half*)outv + oi) = __floats2half2_rn(v0, v1);
                }
            }
        }
    }
}

// ---------------- fp16 tensor-core windowed attention ------------------------
// block = (window, head); 7 warps × 2 m16 tiles (rows padded to 224).
// Keys padded to 224, 4 chunks of 56. QK: m16n8k16. PV: 3×k16 + 1×k8 per chunk
// using the accumulator->A-fragment identity (no shuffles).
#define AQ_STR 40                 // halves per Q/K row
#define AVT_STR 232               // halves per VT row
#define A_SM_HALVES (2*224*AQ_STR + 32*AVT_STR)   // 17920+17920+7424 halves
#define A_SMEM_BYTES (A_SM_HALVES*2)              // 50688 B

__global__ void __launch_bounds__(224, 2)
attn_mma_kernel(const __half* __restrict__ qkv, __half* __restrict__ outp)
{
    extern __shared__ __half smh[];
    __half* Qs = smh;                     // [224][40]
    __half* Ks = smh + 224 * AQ_STR;      // [224][40]
    __half* VT = smh + 2 * 224 * AQ_STR;  // [32][232]  (d-major, key contiguous)

    int blk = blockIdx.x;
    int win = blk / HEADS;
    int head = blk - win * HEADS;
    int b = win / WIN_PER_B;
    int wr = win - b * WIN_PER_B;
    int h0 = (wr / NWIN_SIDE) * WS, w0 = (wr % NWIN_SIDE) * WS;

    int tid = threadIdx.x;
    int lane = tid & 31, warp = tid >> 5;
    int gid = lane >> 2, tig = lane & 3;
    const float scale = 0.17677669529663687f;

    // ---- load Q,K,V (one row per thread)
    {
        int r = tid;
        if (r < NTOKW) {
            int tok = b * HW + (h0 + r / WS) * WW + (w0 + r % WS);
            const uint4* q4 = (const uint4*)(qkv + (size_t)tok * QKV_DIM + head * DHEAD);
            const uint4* k4 = (const uint4*)(qkv + (size_t)tok * QKV_DIM + C + head * DHEAD);
            const uint4* v4 = (const uint4*)(qkv + (size_t)tok * QKV_DIM + 2 * C + head * DHEAD);
            #pragma unroll
            for (int i = 0; i < 4; i++) {
                uint4 qa = q4[i], ka = k4[i], va = v4[i];
                const __half2* qh = (const __half2*)&qa;
                const __half2* vh = (const __half2*)&va;
                #pragma unroll
                for (int j = 0; j < 4; j++) {
                    float2 f = __half22float2(qh[j]);
                    *(__half2*)(Qs + r * AQ_STR + i * 8 + 2 * j) =
                        __floats2half2_rn(f.x * scale, f.y * scale);
                }
                *(uint4*)(Ks + r * AQ_STR + i * 8) = ka;
                #pragma unroll
                for (int j = 0; j < 4; j++) {
                    int e = i * 8 + 2 * j;
                    VT[e * AVT_STR + r]       = __low2half(vh[j]);
                    VT[(e + 1) * AVT_STR + r] = __high2half(vh[j]);
                }
            }
        } else {
            uint4 z = {0, 0, 0, 0};
            #pragma unroll
            for (int i = 0; i < 4; i++) {
                *(uint4*)(Qs + r * AQ_STR + i * 8) = z;
                *(uint4*)(Ks + r * AQ_STR + i * 8) = z;
            }
            #pragma unroll
            for (int e = 0; e < DHEAD; e++) VT[e * AVT_STR + r] = __float2half(0.f);
        }
    }
    __syncthreads();

    float mS[2][2], lS[2][2];
    float O[2][4][4] = {};
    #pragma unroll
    for (int i = 0; i < 2; i++) { mS[i][0] = mS[i][1] = -1e30f; lS[i][0] = lS[i][1] = 0.f; }

    #pragma unroll 1
    for (int ch = 0; ch < 4; ch++) {
        float S[2][7][4] = {};
        // ---- S = Q K^T
        #pragma unroll
        for (int ks = 0; ks < 2; ks++) {
            uint32_t af[2][4];
            #pragma unroll
            for (int mt = 0; mt < 2; mt++) {
                int r = warp * 32 + mt * 16 + gid;
                af[mt][0] = *(const uint32_t*)(Qs + r * AQ_STR + ks * 16 + 2 * tig);
                af[mt][1] = *(const uint32_t*)(Qs + (r + 8) * AQ_STR + ks * 16 + 2 * tig);
                af[mt][2] = *(const uint32_t*)(Qs + r * AQ_STR + ks * 16 + 2 * tig + 8);
                af[mt][3] = *(const uint32_t*)(Qs + (r + 8) * AQ_STR + ks * 16 + 2 * tig + 8);
            }
            #pragma unroll
            for (int nt = 0; nt < 7; nt++) {
                int col = ch * 56 + nt * 8 + gid;
                uint32_t bf[2];
                bf[0] = *(const uint32_t*)(Ks + col * AQ_STR + ks * 16 + 2 * tig);
                bf[1] = *(const uint32_t*)(Ks + col * AQ_STR + ks * 16 + 2 * tig + 8);
                #pragma unroll
                for (int mt = 0; mt < 2; mt++)
                    MMA_F16_K16(S[mt][nt], af[mt], bf);
            }
        }
        // ---- mask padded key columns (last chunk only)
        if (ch == 3) {
            #pragma unroll
            for (int nt = 0; nt < 7; nt++) {
                int col0 = 168 + nt * 8 + 2 * tig;
                if (col0 >= NTOKW) {
                    #pragma unroll
                    for (int u = 0; u < 4; u++) { S[0][nt][u] = -1e30f; S[1][nt][u] = -1e30f; }
                }
            }
        }
        // ---- online softmax
        #pragma unroll
        for (int mt = 0; mt < 2; mt++) {
            #pragma unroll
            for (int hf = 0; hf < 2; hf++) {
                float mc = -1e30f;
                #pragma unroll
                for (int nt = 0; nt < 7; nt++)
                    mc = fmaxf(mc, fmaxf(S[mt][nt][hf * 2], S[mt][nt][hf * 2 + 1]));
                mc = fmaxf(mc, __shfl_xor_sync(0xffffffffu, mc, 1));
                mc = fmaxf(mc, __shfl_xor_sync(0xffffffffu, mc, 2));
                float mn = fmaxf(mS[mt][hf], mc);
                float sc = __expf(mS[mt][hf] - mn);
                float rs = 0.f;
                #pragma unroll
                for (int nt = 0; nt < 7; nt++) {
                    float p0 = __expf(S[mt][nt][hf * 2]     - mn);
                    float p1 = __expf(S[mt][nt][hf * 2 + 1] - mn);
                    S[mt][nt][hf * 2]     = p0;
                    S[mt][nt][hf * 2 + 1] = p1;
                    rs += p0 + p1;
                }
                rs += __shfl_xor_sync(0xffffffffu, rs, 1);
                rs += __shfl_xor_sync(0xffffffffu, rs, 2);
                lS[mt][hf] = lS[mt][hf] * sc + rs;
                mS[mt][hf] = mn;
                #pragma unroll
                for (int nv = 0; nv < 4; nv++) {
                    O[mt][nv][hf * 2]     *= sc;
                    O[mt][nv][hf * 2 + 1] *= sc;
                }
            }
        }
        // ---- O += P V : accumulator IS the A fragment (pack to half2)
        #pragma unroll
        for (int pj = 0; pj < 3; pj++) {       // key pairs (k16)
            uint32_t a[2][4];
            #pragma unroll
            for (int mt = 0; mt < 2; mt++) {
                a[mt][0] = pack_h2(S[mt][2 * pj][0],     S[mt][2 * pj][1]);
                a[mt][1] = pack_h2(S[mt][2 * pj][2],     S[mt][2 * pj][3]);
                a[mt][2] = pack_h2(S[mt][2 * pj + 1][0], S[mt][2 * pj + 1][1]);
                a[mt][3] = pack_h2(S[mt][2 * pj + 1][2], S[mt][2 * pj + 1][3]);
            }
            int key = ch * 56 + pj * 16;
            #pragma unroll
            for (int nv = 0; nv < 4; nv++) {
                uint32_t bf[2];
                bf[0] = *(const uint32_t*)(VT + (nv * 8 + gid) * AVT_STR + key + 2 * tig);
                bf[1] = *(const uint32_t*)(VT + (nv * 8 + gid) * AVT_STR + key + 2 * tig + 8);
                #pragma unroll
                for (int mt = 0; mt < 2; mt++)
                    MMA_F16_K16(O[mt][nv], a[mt], bf);
            }
        }
        {   // leftover tile 6 (k8)
            uint32_t a[2][2];
            #pragma unroll
            for (int mt = 0; mt < 2; mt++) {
                a[mt][0] = pack_h2(S[mt][6][0], S[mt][6][1]);
                a[mt][1] = pack_h2(S[mt][6][2], S[mt][6][3]);
            }
            int key = ch * 56 + 48;
            #pragma unroll
            for (int nv = 0; nv < 4; nv++) {
                uint32_t b0 = *(const uint32_t*)(VT + (nv * 8 + gid) * AVT_STR + key + 2 * tig);
                #pragma unroll
                for (int mt = 0; mt < 2; mt++)
                    MMA_F16_K8(O[mt][nv], a[mt], b0);
            }
        }
    }

    // ---- write output (half; feeds proj GEMM)
    #pragma unroll
    for (int mt = 0; mt < 2; mt++) {
        #pragma unroll
        for (int hf = 0; hf < 2; hf++) {
            int r = warp * 32 + mt * 16 + gid + hf * 8;
            if (r < NTOKW) {
                int tok = b * HW + (h0 + r / WS) * WW + (w0 + r % WS);
                float inv = 1.f / lS[mt][hf];
                __half* op = outp + (size_t)tok * C + head * DHEAD;
                #pragma unroll
                for (int nv = 0; nv < 4; nv++) {
                    int cb2 = nv * 8 + 2 * tig;
                    *(__half2*)(op + cb2) =
                        __floats2half2_rn(O[mt][nv][hf * 2] * inv, O[mt][nv][hf * 2 + 1] * inv);
                }
            }
        }
    }
}

// ---------------- final transpose BHWC -> BCHW -------------------------------
__global__ void transpose_kernel(const float* __restrict__ in, float* __restrict__ out)
{
    __shared__ float tile[32][33];
    int b = blockIdx.z;
    int hw0 = blockIdx.x * 32;
    int c0 = blockIdx.y * 32;
    int txx = threadIdx.x;

    for (int r = threadIdx.y; r < 32; r += 8)
        tile[r][txx] = in[((size_t)b * HW + hw0 + r) * C + c0 + txx];
    __syncthreads();
    for (int r = threadIdx.y; r < 32; r += 8)
        out[((size_t)b * C + c0 + r) * HW + hw0 + txx] = tile[txx][r];
}

// ---------------- launcher ---------------------------------------------------
extern "C" void kernel_launch(void* const* d_in, const int* in_sizes, int n_in,
                              void* d_out, int out_size)
{
    const float* x      = (const float*)d_in[0];
    const float* conv_w = (const float*)d_in[1];
    const float* conv_b = (const float*)d_in[2];
    const float* ln1_w  = (const float*)d_in[3];
    const float* ln1_b  = (const float*)d_in[4];
    const float* qkv_w  = (const float*)d_in[5];
    const float* proj_w = (const float*)d_in[6];
    const float* proj_b = (const float*)d_in[7];
    const float* ln2_w  = (const float*)d_in[8];
    const float* ln2_b  = (const float*)d_in[9];
    const float* fc1_w  = (const float*)d_in[10];
    const float* fc1_b  = (const float*)d_in[11];
    const float* fc2_w  = (const float*)d_in[12];
    const float* fc2_b  = (const float*)d_in[13];
    float* out = (float*)d_out;

    float *p_x1, *p_x2, *p_x3;
    __half *p_xn, *p_qkv, *p_attn, *p_h, *p_wq, *p_wp, *p_w1, *p_w2;
    cudaGetSymbolAddress((void**)&p_x1, g_x1);
    cudaGetSymbolAddress((void**)&p_x2, g_x2);
    cudaGetSymbolAddress((void**)&p_x3, g_x3);
    cudaGetSymbolAddress((void**)&p_xn, g_xn);
    cudaGetSymbolAddress((void**)&p_qkv, g_qkv);
    cudaGetSymbolAddress((void**)&p_attn, g_attn);
    cudaGetSymbolAddress((void**)&p_h, g_h);
    cudaGetSymbolAddress((void**)&p_wq, g_wq);
    cudaGetSymbolAddress((void**)&p_wp, g_wp);
    cudaGetSymbolAddress((void**)&p_w1, g_w1);
    cudaGetSymbolAddress((void**)&p_w2, g_w2);

    const int gemm_smem = 2 * 3 * HST * sizeof(__half);   // 61440
    cudaFuncSetAttribute(hgemm_kernel<0>, cudaFuncAttributeMaxDynamicSharedMemorySize, gemm_smem);
    cudaFuncSetAttribute(hgemm_kernel<1>, cudaFuncAttributeMaxDynamicSharedMemorySize, gemm_smem);
    cudaFuncSetAttribute(hgemm_kernel<2>, cudaFuncAttributeMaxDynamicSharedMemorySize, gemm_smem);
    cudaFuncSetAttribute(attn_mma_kernel, cudaFuncAttributeMaxDynamicSharedMemorySize, A_SMEM_BYTES);

    // 0. convert weights to half
    cvt_weights_kernel<<<(SQ + SP + S1 + S2 + 255) / 256, 256>>>(
        qkv_w, proj_w, fc1_w, fc2_w, p_wq, p_wp, p_w1, p_w2);

    // 1. depthwise conv + bias + residual -> BHWC fp32
    conv_pe_kernel<<<dim3(C / 32, HH, BATCH), 256>>>(x, conv_w, conv_b, p_x1);

    // 2. LN1 -> half
    ln_kernel<<<NTOK, 128>>>(p_x1, ln1_w, ln1_b, p_xn);

    // 3. QKV gemm (half in/out)
    hgemm_kernel<0><<<dim3(QKV_DIM / 128, NTOK / 128), 256, gemm_smem>>>(
        p_xn, p_wq, nullptr, nullptr, p_qkv, NTOK, QKV_DIM, C);

    // 4. windowed attention (fp16 tensor cores)
    attn_mma_kernel<<<NWIN * HEADS, 224, A_SMEM_BYTES>>>(p_qkv, p_attn);

    // 5. proj gemm + bias + residual(x1) -> fp32
    hgemm_kernel<1><<<dim3(C / 128, NTOK / 128), 256, gemm_smem>>>(
        p_attn, p_wp, proj_b, p_x1, p_x2, NTOK, C, C);

    // 6. LN2 -> half
    ln_kernel<<<NTOK, 128>>>(p_x2, ln2_w, ln2_b, p_xn);

    // 7. fc1 gemm + bias + GELU -> half
    hgemm_kernel<2><<<dim3(MLP_HID / 128, NTOK / 128), 256, gemm_smem>>>(
        p_xn, p_w1, fc1_b, nullptr, p_h, NTOK, MLP_HID, C);

    // 8. fc2 gemm + bias + residual(x2) -> fp32
    hgemm_kernel<1><<<dim3(C / 128, NTOK / 128), 256, gemm_smem>>>(
        p_h, p_w2, fc2_b, p_x2, p_x3, NTOK, C, MLP_HID);

    // 9. BHWC -> BCHW
    transpose_kernel<<<dim3(HW / 32, C / 32, BATCH), dim3(32, 8)>>>(p_x3, out);
}

// round 5
// speedup vs baseline: 5.2490x; 1.1546x over previous
#include <cuda_runtime.h>
#include <cuda_fp16.h>
#include <math.h>
#include <stdint.h>

// Problem constants
#define BATCH 16
#define C 384
#define HH 56
#define WW 56
#define HW (HH*WW)            // 3136
#define NTOK (BATCH*HW)       // 50176
#define HEADS 12
#define DHEAD 32
#define WS 14
#define NWIN_SIDE 4
#define WIN_PER_B 16
#define NWIN (BATCH*WIN_PER_B) // 256
#define NTOKW (WS*WS)          // 196
#define MLP_HID (4*C)          // 1536
#define QKV_DIM (3*C)          // 1152

// ---------------- scratch buffers -------------------------------------------
__device__ float  g_x1[(size_t)NTOK * C];        // residual stream fp32
__device__ float  g_x2[(size_t)NTOK * C];
__device__ float  g_x3[(size_t)NTOK * C];
__device__ __half g_xn[(size_t)NTOK * C];        // LN out (half)
__device__ __half g_qkv[(size_t)NTOK * QKV_DIM];
__device__ __half g_attn[(size_t)NTOK * C];
__device__ __half g_h[(size_t)NTOK * MLP_HID];
// half weight copies
__device__ __half g_wq[(size_t)QKV_DIM * C];
__device__ __half g_wp[(size_t)C * C];
__device__ __half g_w1[(size_t)MLP_HID * C];
__device__ __half g_w2[(size_t)C * MLP_HID];

__device__ __forceinline__ uint32_t pack_h2(float a, float b) {
    __half2 h = __floats2half2_rn(a, b);
    return *reinterpret_cast<uint32_t*>(&h);
}

#define MMA_F16_K16(d, a, b)                                           \
    asm volatile(                                                      \
        "mma.sync.aligned.m16n8k16.row.col.f32.f16.f16.f32 "           \
        "{%0,%1,%2,%3},{%4,%5,%6,%7},{%8,%9},{%0,%1,%2,%3};\n"         \
        : "+f"(d[0]), "+f"(d[1]), "+f"(d[2]), "+f"(d[3])               \
        : "r"(a[0]), "r"(a[1]), "r"(a[2]), "r"(a[3]), "r"(b[0]), "r"(b[1]))

#define MMA_F16_K8(d, a, b0)                                           \
    asm volatile(                                                      \
        "mma.sync.aligned.m16n8k8.row.col.f32.f16.f16.f32 "            \
        "{%0,%1,%2,%3},{%4,%5},{%6},{%0,%1,%2,%3};\n"                  \
        : "+f"(d[0]), "+f"(d[1]), "+f"(d[2]), "+f"(d[3])               \
        : "r"(a[0]), "r"(a[1]), "r"(b0))

#define LDMATRIX_X4(r0, r1, r2, r3, addr)                              \
    asm volatile("ldmatrix.sync.aligned.m8n8.x4.shared.b16 "           \
                 "{%0,%1,%2,%3}, [%4];"                                \
                 : "=r"(r0), "=r"(r1), "=r"(r2), "=r"(r3) : "r"(addr))

__device__ __forceinline__ void cpasync16(void* smem_dst, const void* gsrc) {
    uint32_t s = (uint32_t)__cvta_generic_to_shared(smem_dst);
    asm volatile("cp.async.cg.shared.global [%0], [%1], 16;" :: "r"(s), "l"(gsrc));
}

// ---------------- weight conversion fp32 -> fp16 (single kernel) -------------
#define SQ (QKV_DIM*C)
#define SP (C*C)
#define S1 (MLP_HID*C)
#define S2 (C*MLP_HID)
__global__ void cvt_weights_kernel(const float* __restrict__ wq, const float* __restrict__ wp,
                                   const float* __restrict__ w1, const float* __restrict__ w2,
                                   __half* oq, __half* op_, __half* o1, __half* o2)
{
    int i = blockIdx.x * 256 + threadIdx.x;
    if (i < SQ) oq[i] = __float2half(wq[i]);
    else if (i < SQ + SP) op_[i - SQ] = __float2half(wp[i - SQ]);
    else if (i < SQ + SP + S1) o1[i - SQ - SP] = __float2half(w1[i - SQ - SP]);
    else if (i < SQ + SP + S1 + S2) o2[i - SQ - SP - S1] = __float2half(w2[i - SQ - SP - S1]);
}

// ---------------- depthwise conv + bias + residual, NCHW -> BHWC -------------
__global__ void conv_pe_kernel(const float* __restrict__ x,
                               const float* __restrict__ cw,
                               const float* __restrict__ cb,
                               float* __restrict__ out)
{
    __shared__ float sx[3][58][33];
    int c0 = blockIdx.x * 32;
    int h  = blockIdx.y;
    int b  = blockIdx.z;
    int tid = threadIdx.x;

    for (int idx = tid; idx < 32 * 3 * 58; idx += 256) {
        int wq = idx % 58;
        int t  = idx / 58;
        int hh = t % 3;
        int c  = t / 3;
        int gh = h + hh - 1, gw = wq - 1;
        float v = 0.f;
        if (gh >= 0 && gh < HH && gw >= 0 && gw < WW)
            v = x[(size_t)(b * C + c0 + c) * HW + gh * WW + gw];
        sx[hh][wq][c] = v;
    }
    __syncthreads();

    for (int o = tid; o < 32 * WW; o += 256) {
        int c = o & 31, w = o >> 5;
        const float* wt = cw + (size_t)(c0 + c) * 9;
        float s = cb[c0 + c] + sx[1][w + 1][c];
        #pragma unroll
        for (int dy = 0; dy < 3; dy++)
            #pragma unroll
            for (int dx = 0; dx < 3; dx++)
                s += sx[dy][w + dx][c] * wt[dy * 3 + dx];
        out[(size_t)(b * HW + h * WW + w) * C + c0 + c] = s;
    }
}

// ---------------- layer norm over C=384, half output -------------------------
__global__ void ln_kernel(const float* __restrict__ x,
                          const float* __restrict__ w,
                          const float* __restrict__ b,
                          __half* __restrict__ y)
{
    __shared__ float red[4];
    int t = blockIdx.x;
    int tid = threadIdx.x;
    const float* xr = x + (size_t)t * C;

    float v0 = xr[tid];
    float v1 = xr[tid + 128];
    float v2 = xr[tid + 256];

    float s = v0 + v1 + v2;
    for (int o = 16; o > 0; o >>= 1) s += __shfl_down_sync(0xffffffffu, s, o);
    if ((tid & 31) == 0) red[tid >> 5] = s;
    __syncthreads();
    float tot = red[0] + red[1] + red[2] + red[3];
    float mean = tot * (1.0f / C);

    float d0 = v0 - mean, d1 = v1 - mean, d2 = v2 - mean;
    float q = d0 * d0 + d1 * d1 + d2 * d2;
    __syncthreads();
    for (int o = 16; o > 0; o >>= 1) q += __shfl_down_sync(0xffffffffu, q, o);
    if ((tid & 31) == 0) red[tid >> 5] = q;
    __syncthreads();
    float var = (red[0] + red[1] + red[2] + red[3]) * (1.0f / C);
    float rstd = rsqrtf(var + 1e-5f);

    __half* yr = y + (size_t)t * C;
    yr[tid]       = __float2half(d0 * rstd * w[tid]       + b[tid]);
    yr[tid + 128] = __float2half(d1 * rstd * w[tid + 128] + b[tid + 128]);
    yr[tid + 256] = __float2half(d2 * rstd * w[tid + 256] + b[tid + 256]);
}

// ---------------- fp16 tensor-core GEMM, cp.async 3-stage, ldmatrix ----------
// out[M,N] = A[M,K] @ W[N,K]^T ; EPI 0 plain->half, 1 +bias+res->f32,
// 2 +bias+GELU->half. 128x128x32 tile, 8 warps, smem [row][40] halves.
#define HST (128*40)   // halves per stage per matrix

template<int EPI>
__global__ void __launch_bounds__(256, 2)
hgemm_kernel(const __half* __restrict__ A, const __half* __restrict__ W,
             const float* __restrict__ bias, const float* __restrict__ res,
             void* __restrict__ outv, int M, int N, int K)
{
    extern __shared__ __half smh[];
    __half* As = smh;            // [3][128][40]
    __half* Bs = smh + 3 * HST;

    int tid = threadIdx.x;
    int lane = tid & 31, warp = tid >> 5;
    int warpM = (warp >> 1) * 32;
    int warpN = (warp & 1) * 64;
    int gid = lane >> 2, tig = lane & 3;

    const __half* Abase = A + (size_t)(blockIdx.y * 128) * K;
    const __half* Wbase = W + (size_t)(blockIdx.x * 128) * K;
    int nk = K >> 5;

    // ldmatrix base byte-offsets (stage 0, ks 0)
    uint32_t smA = (uint32_t)__cvta_generic_to_shared(As);
    uint32_t smB = (uint32_t)__cvta_generic_to_shared(Bs);
    // A: lanes 0-15 rows m0-15 (k0-7), lanes 16-31 same rows k8-15
    uint32_t aAddr[2];
    #pragma unroll
    for (int mt = 0; mt < 2; mt++)
        aAddr[mt] = smA + (((warpM + mt * 16 + (lane & 15)) * 40 + (lane >> 4) * 8) << 1);
    // B: pair ntp covers nt=2*ntp (lanes 0-15) and nt=2*ntp+1 (lanes 16-31)
    uint32_t bAddr[4];
    #pragma unroll
    for (int ntp = 0; ntp < 4; ntp++)
        bAddr[ntp] = smB + (((warpN + ntp * 16 + (lane & 7) + ((lane >> 4) << 3)) * 40
                             + (((lane >> 3) & 1) * 8)) << 1);

    auto issue = [&](int kt) {
        int st = kt % 3;
        #pragma unroll
        for (int i = 0; i < 2; i++) {
            int chunk = i * 256 + tid;           // 0..511
            int row = chunk >> 2, kc = chunk & 3;
            cpasync16(As + st * HST + row * 40 + kc * 8,
                      Abase + (size_t)row * K + kt * 32 + kc * 8);
        }
        #pragma unroll
        for (int i = 0; i < 2; i++) {
            int chunk = i * 256 + tid;
            int row = chunk >> 2, kc = chunk & 3;
            cpasync16(Bs + st * HST + row * 40 + kc * 8,
                      Wbase + (size_t)row * K + kt * 32 + kc * 8);
        }
    };

    issue(0); asm volatile("cp.async.commit_group;");
    issue(1); asm volatile("cp.async.commit_group;");

    float acc[2][8][4] = {};

    for (int kt = 0; kt < nk; kt++) {
        asm volatile("cp.async.wait_group 1;");
        __syncthreads();
        if (kt + 2 < nk) issue(kt + 2);
        asm volatile("cp.async.commit_group;");

        uint32_t stoff = (uint32_t)((kt % 3) * HST * 2);

        #pragma unroll
        for (int ks = 0; ks < 2; ks++) {
            uint32_t af[2][4], bf[8][2];
            #pragma unroll
            for (int mt = 0; mt < 2; mt++)
                LDMATRIX_X4(af[mt][0], af[mt][1], af[mt][2], af[mt][3],
                            aAddr[mt] + stoff + ks * 32);
            #pragma unroll
            for (int ntp = 0; ntp < 4; ntp++)
                LDMATRIX_X4(bf[2 * ntp][0], bf[2 * ntp][1], bf[2 * ntp + 1][0], bf[2 * ntp + 1][1],
                            bAddr[ntp] + stoff + ks * 32);
            #pragma unroll
            for (int mt = 0; mt < 2; mt++)
                #pragma unroll
                for (int nt = 0; nt < 8; nt++)
                    MMA_F16_K16(acc[mt][nt], af[mt], bf[nt]);
        }
    }

    #pragma unroll
    for (int mt = 0; mt < 2; mt++) {
        #pragma unroll
        for (int half = 0; half < 2; half++) {
            int r = blockIdx.y * 128 + warpM + mt * 16 + gid + half * 8;
            #pragma unroll
            for (int nt = 0; nt < 8; nt++) {
                int cc = blockIdx.x * 128 + warpN + nt * 8 + 2 * tig;
                float v0 = acc[mt][nt][half * 2 + 0];
                float v1 = acc[mt][nt][half * 2 + 1];
                size_t oi = (size_t)r * N + cc;
                if (EPI == 1) {
                    v0 += bias[cc]     + res[oi];
                    v1 += bias[cc + 1] + res[oi + 1];
                    ((float*)outv)[oi]     = v0;
                    ((float*)outv)[oi + 1] = v1;
                } else {
                    if (EPI == 2) {
                        v0 += bias[cc];
                        v1 += bias[cc + 1];
                        v0 = 0.5f * v0 * (1.0f + erff(v0 * 0.70710678118654752f));
                        v1 = 0.5f * v1 * (1.0f + erff(v1 * 0.70710678118654752f));
                    }
                    *(__half2*)((__half*)outv + oi) = __floats2half2_rn(v0, v1);
                }
            }
        }
    }
}

// ---------------- fp16 tensor-core windowed attention ------------------------
#define AQ_STR 40                 // halves per Q/K row
#define AVT_STR 232               // halves per VT row
#define A_SM_HALVES (2*224*AQ_STR + 32*AVT_STR)
#define A_SMEM_BYTES (A_SM_HALVES*2)              // 50688 B

__global__ void __launch_bounds__(224, 2)
attn_mma_kernel(const __half* __restrict__ qkv, __half* __restrict__ outp)
{
    extern __shared__ __half smh[];
    __half* Qs = smh;                     // [224][40]
    __half* Ks = smh + 224 * AQ_STR;      // [224][40]
    __half* VT = smh + 2 * 224 * AQ_STR;  // [32][232]

    int blk = blockIdx.x;
    int win = blk / HEADS;
    int head = blk - win * HEADS;
    int b = win / WIN_PER_B;
    int wr = win - b * WIN_PER_B;
    int h0 = (wr / NWIN_SIDE) * WS, w0 = (wr % NWIN_SIDE) * WS;

    int tid = threadIdx.x;
    int lane = tid & 31, warp = tid >> 5;
    int gid = lane >> 2, tig = lane & 3;
    const float scale = 0.17677669529663687f;

    {
        int r = tid;
        if (r < NTOKW) {
            int tok = b * HW + (h0 + r / WS) * WW + (w0 + r % WS);
            const uint4* q4 = (const uint4*)(qkv + (size_t)tok * QKV_DIM + head * DHEAD);
            const uint4* k4 = (const uint4*)(qkv + (size_t)tok * QKV_DIM + C + head * DHEAD);
            const uint4* v4 = (const uint4*)(qkv + (size_t)tok * QKV_DIM + 2 * C + head * DHEAD);
            #pragma unroll
            for (int i = 0; i < 4; i++) {
                uint4 qa = q4[i], ka = k4[i], va = v4[i];
                const __half2* qh = (const __half2*)&qa;
                const __half2* vh = (const __half2*)&va;
                #pragma unroll
                for (int j = 0; j < 4; j++) {
                    float2 f = __half22float2(qh[j]);
                    *(__half2*)(Qs + r * AQ_STR + i * 8 + 2 * j) =
                        __floats2half2_rn(f.x * scale, f.y * scale);
                }
                *(uint4*)(Ks + r * AQ_STR + i * 8) = ka;
                #pragma unroll
                for (int j = 0; j < 4; j++) {
                    int e = i * 8 + 2 * j;
                    VT[e * AVT_STR + r]       = __low2half(vh[j]);
                    VT[(e + 1) * AVT_STR + r] = __high2half(vh[j]);
                }
            }
        } else {
            uint4 z = {0, 0, 0, 0};
            #pragma unroll
            for (int i = 0; i < 4; i++) {
                *(uint4*)(Qs + r * AQ_STR + i * 8) = z;
                *(uint4*)(Ks + r * AQ_STR + i * 8) = z;
            }
            #pragma unroll
            for (int e = 0; e < DHEAD; e++) VT[e * AVT_STR + r] = __float2half(0.f);
        }
    }
    __syncthreads();

    float mS[2][2], lS[2][2];
    float O[2][4][4] = {};
    #pragma unroll
    for (int i = 0; i < 2; i++) { mS[i][0] = mS[i][1] = -1e30f; lS[i][0] = lS[i][1] = 0.f; }

    #pragma unroll 1
    for (int ch = 0; ch < 4; ch++) {
        float S[2][7][4] = {};
        #pragma unroll
        for (int ks = 0; ks < 2; ks++) {
            uint32_t af[2][4];
            #pragma unroll
            for (int mt = 0; mt < 2; mt++) {
                int r = warp * 32 + mt * 16 + gid;
                af[mt][0] = *(const uint32_t*)(Qs + r * AQ_STR + ks * 16 + 2 * tig);
                af[mt][1] = *(const uint32_t*)(Qs + (r + 8) * AQ_STR + ks * 16 + 2 * tig);
                af[mt][2] = *(const uint32_t*)(Qs + r * AQ_STR + ks * 16 + 2 * tig + 8);
                af[mt][3] = *(const uint32_t*)(Qs + (r + 8) * AQ_STR + ks * 16 + 2 * tig + 8);
            }
            #pragma unroll
            for (int nt = 0; nt < 7; nt++) {
                int col = ch * 56 + nt * 8 + gid;
                uint32_t bf[2];
                bf[0] = *(const uint32_t*)(Ks + col * AQ_STR + ks * 16 + 2 * tig);
                bf[1] = *(const uint32_t*)(Ks + col * AQ_STR + ks * 16 + 2 * tig + 8);
                #pragma unroll
                for (int mt = 0; mt < 2; mt++)
                    MMA_F16_K16(S[mt][nt], af[mt], bf);
            }
        }
        if (ch == 3) {
            #pragma unroll
            for (int nt = 0; nt < 7; nt++) {
                int col0 = 168 + nt * 8 + 2 * tig;
                if (col0 >= NTOKW) {
                    #pragma unroll
                    for (int u = 0; u < 4; u++) { S[0][nt][u] = -1e30f; S[1][nt][u] = -1e30f; }
                }
            }
        }
        #pragma unroll
        for (int mt = 0; mt < 2; mt++) {
            #pragma unroll
            for (int hf = 0; hf < 2; hf++) {
                float mc = -1e30f;
                #pragma unroll
                for (int nt = 0; nt < 7; nt++)
                    mc = fmaxf(mc, fmaxf(S[mt][nt][hf * 2], S[mt][nt][hf * 2 + 1]));
                mc = fmaxf(mc, __shfl_xor_sync(0xffffffffu, mc, 1));
                mc = fmaxf(mc, __shfl_xor_sync(0xffffffffu, mc, 2));
                float mn = fmaxf(mS[mt][hf], mc);
                float sc = __expf(mS[mt][hf] - mn);
                float rs = 0.f;
                #pragma unroll
                for (int nt = 0; nt < 7; nt++) {
                    float p0 = __expf(S[mt][nt][hf * 2]     - mn);
                    float p1 = __expf(S[mt][nt][hf * 2 + 1] - mn);
                    S[mt][nt][hf * 2]     = p0;
                    S[mt][nt][hf * 2 + 1] = p1;
                    rs += p0 + p1;
                }
                rs += __shfl_xor_sync(0xffffffffu, rs, 1);
                rs += __shfl_xor_sync(0xffffffffu, rs, 2);
                lS[mt][hf] = lS[mt][hf] * sc + rs;
                mS[mt][hf] = mn;
                #pragma unroll
                for (int nv = 0; nv < 4; nv++) {
                    O[mt][nv][hf * 2]     *= sc;
                    O[mt][nv][hf * 2 + 1] *= sc;
                }
            }
        }
        #pragma unroll
        for (int pj = 0; pj < 3; pj++) {
            uint32_t a[2][4];
            #pragma unroll
            for (int mt = 0; mt < 2; mt++) {
                a[mt][0] = pack_h2(S[mt][2 * pj][0],     S[mt][2 * pj][1]);
                a[mt][1] = pack_h2(S[mt][2 * pj][2],     S[mt][2 * pj][3]);
                a[mt][2] = pack_h2(S[mt][2 * pj + 1][0], S[mt][2 * pj + 1][1]);
                a[mt][3] = pack_h2(S[mt][2 * pj + 1][2], S[mt][2 * pj + 1][3]);
            }
            int key = ch * 56 + pj * 16;
            #pragma unroll
            for (int nv = 0; nv < 4; nv++) {
                uint32_t bf[2];
                bf[0] = *(const uint32_t*)(VT + (nv * 8 + gid) * AVT_STR + key + 2 * tig);
                bf[1] = *(const uint32_t*)(VT + (nv * 8 + gid) * AVT_STR + key + 2 * tig + 8);
                #pragma unroll
                for (int mt = 0; mt < 2; mt++)
                    MMA_F16_K16(O[mt][nv], a[mt], bf);
            }
        }
        {
            uint32_t a[2][2];
            #pragma unroll
            for (int mt = 0; mt < 2; mt++) {
                a[mt][0] = pack_h2(S[mt][6][0], S[mt][6][1]);
                a[mt][1] = pack_h2(S[mt][6][2], S[mt][6][3]);
            }
            int key = ch * 56 + 48;
            #pragma unroll
            for (int nv = 0; nv < 4; nv++) {
                uint32_t b0 = *(const uint32_t*)(VT + (nv * 8 + gid) * AVT_STR + key + 2 * tig);
                #pragma unroll
                for (int mt = 0; mt < 2; mt++)
                    MMA_F16_K8(O[mt][nv], a[mt], b0);
            }
        }
    }

    #pragma unroll
    for (int mt = 0; mt < 2; mt++) {
        #pragma unroll
        for (int hf = 0; hf < 2; hf++) {
            int r = warp * 32 + mt * 16 + gid + hf * 8;
            if (r < NTOKW) {
                int tok = b * HW + (h0 + r / WS) * WW + (w0 + r % WS);
                float inv = 1.f / lS[mt][hf];
                __half* op = outp + (size_t)tok * C + head * DHEAD;
                #pragma unroll
                for (int nv = 0; nv < 4; nv++) {
                    int cb2 = nv * 8 + 2 * tig;
                    *(__half2*)(op + cb2) =
                        __floats2half2_rn(O[mt][nv][hf * 2] * inv, O[mt][nv][hf * 2 + 1] * inv);
                }
            }
        }
    }
}

// ---------------- final transpose BHWC -> BCHW -------------------------------
__global__ void transpose_kernel(const float* __restrict__ in, float* __restrict__ out)
{
    __shared__ float tile[32][33];
    int b = blockIdx.z;
    int hw0 = blockIdx.x * 32;
    int c0 = blockIdx.y * 32;
    int txx = threadIdx.x;

    for (int r = threadIdx.y; r < 32; r += 8)
        tile[r][txx] = in[((size_t)b * HW + hw0 + r) * C + c0 + txx];
    __syncthreads();
    for (int r = threadIdx.y; r < 32; r += 8)
        out[((size_t)b * C + c0 + r) * HW + hw0 + txx] = tile[txx][r];
}

// ---------------- launcher ---------------------------------------------------
extern "C" void kernel_launch(void* const* d_in, const int* in_sizes, int n_in,
                              void* d_out, int out_size)
{
    const float* x      = (const float*)d_in[0];
    const float* conv_w = (const float*)d_in[1];
    const float* conv_b = (const float*)d_in[2];
    const float* ln1_w  = (const float*)d_in[3];
    const float* ln1_b  = (const float*)d_in[4];
    const float* qkv_w  = (const float*)d_in[5];
    const float* proj_w = (const float*)d_in[6];
    const float* proj_b = (const float*)d_in[7];
    const float* ln2_w  = (const float*)d_in[8];
    const float* ln2_b  = (const float*)d_in[9];
    const float* fc1_w  = (const float*)d_in[10];
    const float* fc1_b  = (const float*)d_in[11];
    const float* fc2_w  = (const float*)d_in[12];
    const float* fc2_b  = (const float*)d_in[13];
    float* out = (float*)d_out;

    float *p_x1, *p_x2, *p_x3;
    __half *p_xn, *p_qkv, *p_attn, *p_h, *p_wq, *p_wp, *p_w1, *p_w2;
    cudaGetSymbolAddress((void**)&p_x1, g_x1);
    cudaGetSymbolAddress((void**)&p_x2, g_x2);
    cudaGetSymbolAddress((void**)&p_x3, g_x3);
    cudaGetSymbolAddress((void**)&p_xn, g_xn);
    cudaGetSymbolAddress((void**)&p_qkv, g_qkv);
    cudaGetSymbolAddress((void**)&p_attn, g_attn);
    cudaGetSymbolAddress((void**)&p_h, g_h);
    cudaGetSymbolAddress((void**)&p_wq, g_wq);
    cudaGetSymbolAddress((void**)&p_wp, g_wp);
    cudaGetSymbolAddress((void**)&p_w1, g_w1);
    cudaGetSymbolAddress((void**)&p_w2, g_w2);

    const int gemm_smem = 2 * 3 * HST * sizeof(__half);   // 61440
    cudaFuncSetAttribute(hgemm_kernel<0>, cudaFuncAttributeMaxDynamicSharedMemorySize, gemm_smem);
    cudaFuncSetAttribute(hgemm_kernel<1>, cudaFuncAttributeMaxDynamicSharedMemorySize, gemm_smem);
    cudaFuncSetAttribute(hgemm_kernel<2>, cudaFuncAttributeMaxDynamicSharedMemorySize, gemm_smem);
    cudaFuncSetAttribute(attn_mma_kernel, cudaFuncAttributeMaxDynamicSharedMemorySize, A_SMEM_BYTES);

    // 0. convert weights to half
    cvt_weights_kernel<<<(SQ + SP + S1 + S2 + 255) / 256, 256>>>(
        qkv_w, proj_w, fc1_w, fc2_w, p_wq, p_wp, p_w1, p_w2);

    // 1. depthwise conv + bias + residual -> BHWC fp32
    conv_pe_kernel<<<dim3(C / 32, HH, BATCH), 256>>>(x, conv_w, conv_b, p_x1);

    // 2. LN1 -> half
    ln_kernel<<<NTOK, 128>>>(p_x1, ln1_w, ln1_b, p_xn);

    // 3. QKV gemm (half in/out)
    hgemm_kernel<0><<<dim3(QKV_DIM / 128, NTOK / 128), 256, gemm_smem>>>(
        p_xn, p_wq, nullptr, nullptr, p_qkv, NTOK, QKV_DIM, C);

    // 4. windowed attention (fp16 tensor cores)
    attn_mma_kernel<<<NWIN * HEADS, 224, A_SMEM_BYTES>>>(p_qkv, p_attn);

    // 5. proj gemm + bias + residual(x1) -> fp32
    hgemm_kernel<1><<<dim3(C / 128, NTOK / 128), 256, gemm_smem>>>(
        p_attn, p_wp, proj_b, p_x1, p_x2, NTOK, C, C);

    // 6. LN2 -> half
    ln_kernel<<<NTOK, 128>>>(p_x2, ln2_w, ln2_b, p_xn);

    // 7. fc1 gemm + bias + GELU -> half
    hgemm_kernel<2><<<dim3(MLP_HID / 128, NTOK / 128), 256, gemm_smem>>>(
        p_xn, p_w1, fc1_b, nullptr, p_h, NTOK, MLP_HID, C);

    // 8. fc2 gemm + bias + residual(x2) -> fp32
    hgemm_kernel<1><<<dim3(C / 128, NTOK / 128), 256, gemm_smem>>>(
        p_h, p_w2, fc2_b, p_x2, p_x3, NTOK, C, MLP_HID);

    // 9. BHWC -> BCHW
    transpose_kernel<<<dim3(HW / 32, C / 32, BATCH), dim3(32, 8)>>>(p_x3, out);
}